// round 13
// baseline (speedup 1.0000x reference)
#include <cuda_runtime.h>
#include <cuda_bf16.h>
#include <cstdint>

// R13: R12 + term-major MMA ordering (break 3-deep dependent MMA chains per
// accumulator: issue all term-1 MMAs across accumulators, then term-2, then
// term-3; B-lo fragment loads hidden under term-2). Accumulation order per
// accumulator unchanged -> rel_err must stay exactly 5.018873e-06.

static __forceinline__ __device__ float lrelu(float v) { return v > 0.0f ? v : 0.01f * v; }

constexpr int DEPTH = 18;
// big-level kernel smem map
constexpr int SA_HI = 0;        // [64][528B] bf16
constexpr int SA_LO = 33792;
constexpr int W_ST  = 67584;    // 2 slots x 16896
constexpr int SB1   = 101376;
constexpr int SB2   = 102400;
constexpr int SBE   = 102912;
constexpr int SMEM_LVL = 103424;

// slab64 kernels smem map
constexpr int S_W   = 67584;              // 2 slots x 67584
constexpr int S_SB1 = 202752;
constexpr int S_SB2 = 203776;
constexpr int SMEM_SMALL = 204288;

// prepped split weights (row-major bf16)
__device__ __align__(16) __nv_bfloat16 W1hi_d[65536];   // [256][256]
__device__ __align__(16) __nv_bfloat16 W1lo_d[65536];
__device__ __align__(16) __nv_bfloat16 W2hi_d[32768];   // [256][128]
__device__ __align__(16) __nv_bfloat16 W2lo_d[32768];
__device__ __align__(16) __nv_bfloat16 WBhi_d[16384];   // blockdiag(We,We) [64][256]
__device__ __align__(16) __nv_bfloat16 WBlo_d[16384];

static __forceinline__ __device__ uint32_t smem_u32(const void* p) {
    uint32_t a;
    asm("{ .reg .u64 t; cvta.to.shared.u64 t, %1; cvt.u32.u64 %0, t; }" : "=r"(a) : "l"(p));
    return a;
}
static __forceinline__ __device__ void cp16(uint32_t d, const void* s) {
    asm volatile("cp.async.cg.shared.global [%0], [%1], 16;" :: "r"(d), "l"(s));
}
#define CP_COMMIT() asm volatile("cp.async.commit_group;" ::: "memory")
#define CP_WAIT(N)  asm volatile("cp.async.wait_group %0;" :: "n"(N) : "memory")

static __forceinline__ __device__ void ldsm4(unsigned* r, uint32_t a) {
    asm volatile("ldmatrix.sync.aligned.m8n8.x4.shared.b16 {%0,%1,%2,%3}, [%4];"
                 : "=r"(r[0]), "=r"(r[1]), "=r"(r[2]), "=r"(r[3]) : "r"(a));
}
static __forceinline__ __device__ void ldsm4t(unsigned* r, uint32_t a) {
    asm volatile("ldmatrix.sync.aligned.m8n8.x4.trans.shared.b16 {%0,%1,%2,%3}, [%4];"
                 : "=r"(r[0]), "=r"(r[1]), "=r"(r[2]), "=r"(r[3]) : "r"(a));
}
static __forceinline__ __device__ void mma_bf16(float* c, const unsigned* a, const unsigned* b) {
    asm volatile("mma.sync.aligned.m16n8k16.row.col.f32.bf16.bf16.f32 "
                 "{%0,%1,%2,%3}, {%4,%5,%6,%7}, {%8,%9}, {%0,%1,%2,%3};"
                 : "+f"(c[0]), "+f"(c[1]), "+f"(c[2]), "+f"(c[3])
                 : "r"(a[0]), "r"(a[1]), "r"(a[2]), "r"(a[3]), "r"(b[0]), "r"(b[1]));
}
static __forceinline__ __device__ void split2(float h0, float h1,
                                              __nv_bfloat162& hi, __nv_bfloat162& lo) {
    hi = __floats2bfloat162_rn(h0, h1);
    lo = __floats2bfloat162_rn(h0 - __bfloat162float(hi.x), h1 - __bfloat162float(hi.y));
}

__global__ void prep_kernel(const float* __restrict__ W1, const float* __restrict__ W2,
                            const float* __restrict__ We) {
    int t = blockIdx.x * 256 + threadIdx.x;
    if (t < 65536) {
        float f = W1[t];
        __nv_bfloat16 hi = __float2bfloat16(f);
        W1hi_d[t] = hi; W1lo_d[t] = __float2bfloat16(f - __bfloat162float(hi));
    }
    if (t < 32768) {
        float f = W2[t];
        __nv_bfloat16 hi = __float2bfloat16(f);
        W2hi_d[t] = hi; W2lo_d[t] = __float2bfloat16(f - __bfloat162float(hi));
    }
    if (t < 16384) {
        int k = t >> 8, c = t & 255;
        float f = 0.0f;
        if (k < 32 && c < 128)   f = We[k * 128 + c];
        if (k >= 32 && c >= 128) f = We[(k - 32) * 128 + (c - 128)];
        __nv_bfloat16 hi = __float2bfloat16(f);
        WBhi_d[t] = hi; WBlo_d[t] = __float2bfloat16(f - __bfloat162float(hi));
    }
}

// ---------- big-level slab loader (16 k-rows) ----------
template<bool LEAF>
static __forceinline__ __device__ void load_slab(int g, uint32_t base, int tid) {
    uint32_t slot = base + W_ST + (uint32_t)(g & 1) * 16896u;
    const char *hi, *lo;
    bool k256;
    if (LEAF) {
        if (g < 4)       { hi = (const char*)WBhi_d + (size_t)g * 8192;        lo = (const char*)WBlo_d + (size_t)g * 8192;        k256 = true; }
        else if (g < 20) { hi = (const char*)W1hi_d + (size_t)(g - 4) * 8192;  lo = (const char*)W1lo_d + (size_t)(g - 4) * 8192;  k256 = true; }
        else             { hi = (const char*)W2hi_d + (size_t)(g - 20) * 4096; lo = (const char*)W2lo_d + (size_t)(g - 20) * 4096; k256 = false; }
    } else {
        if (g < 16)      { hi = (const char*)W1hi_d + (size_t)g * 8192;        lo = (const char*)W1lo_d + (size_t)g * 8192;        k256 = true; }
        else             { hi = (const char*)W2hi_d + (size_t)(g - 16) * 4096; lo = (const char*)W2lo_d + (size_t)(g - 16) * 4096; k256 = false; }
    }
    if (k256) {
        #pragma unroll
        for (int j = 0; j < 4; ++j) {
            int idx = tid + j * 256;
            int part = idx >> 9, rc = idx & 511, r = rc >> 5, c = rc & 31;
            cp16(slot + part * 8448 + r * 528 + c * 16, (part ? lo : hi) + r * 512 + c * 16);
        }
    } else {
        #pragma unroll
        for (int j = 0; j < 2; ++j) {
            int idx = tid + j * 256;
            int part = idx >> 8, rc = idx & 255, r = rc >> 4, c = rc & 15;
            cp16(slot + part * 4352 + r * 272 + c * 16, (part ? lo : hi) + r * 256 + c * 16);
        }
    }
    CP_COMMIT();
}

// ---------- slab64 loader: g 0..3 -> W1 64-row slabs, 4..7 -> W2 ----------
static __forceinline__ __device__ void load_slab64(int g, uint32_t wbase, int tid) {
    uint32_t slot = wbase + (uint32_t)(g & 1) * 67584u;
    if (g < 4) {
        const char* hi = (const char*)W1hi_d + (size_t)g * 32768;
        const char* lo = (const char*)W1lo_d + (size_t)g * 32768;
        #pragma unroll
        for (int j = 0; j < 16; ++j) {
            int idx = tid + j * 256;
            int part = idx >> 11, rc = idx & 2047, r = rc >> 5, c = rc & 31;
            cp16(slot + part * 33792 + r * 528 + c * 16, (part ? lo : hi) + r * 512 + c * 16);
        }
    } else {
        const char* hi = (const char*)W2hi_d + (size_t)(g - 4) * 16384;
        const char* lo = (const char*)W2lo_d + (size_t)(g - 4) * 16384;
        #pragma unroll
        for (int j = 0; j < 8; ++j) {
            int idx = tid + j * 256;
            int part = idx >> 10, rc = idx & 1023, r = rc >> 4, c = rc & 15;
            cp16(slot + part * 17408 + r * 272 + c * 16, (part ? lo : hi) + r * 256 + c * 16);
        }
    }
    CP_COMMIT();
}

// ---------- term-major compute helpers ----------
// K256 sub-stage (layer1/emb): bstride = row stride of B slab, lo_off = hi->lo offset
static __forceinline__ __device__ void compute_k256(
    float accA[2][8][4], const unsigned ah[2][4], const unsigned al[2][4],
    uint32_t brow, uint32_t lo_off, int nq, int lcol8)
{
    unsigned bh[4][4];
    #pragma unroll
    for (int p = 0; p < 4; ++p)
        ldsm4t(bh[p], brow + (uint32_t)(nq * 64 + p * 16 + lcol8) * 2);
    #pragma unroll
    for (int p = 0; p < 4; ++p)
        #pragma unroll
        for (int m = 0; m < 2; ++m) {
            mma_bf16(accA[m][2 * p],     ah[m], bh[p]);
            mma_bf16(accA[m][2 * p + 1], ah[m], bh[p] + 2);
        }
    unsigned bl[4][4];
    #pragma unroll
    for (int p = 0; p < 4; ++p)
        ldsm4t(bl[p], brow + lo_off + (uint32_t)(nq * 64 + p * 16 + lcol8) * 2);
    #pragma unroll
    for (int p = 0; p < 4; ++p)
        #pragma unroll
        for (int m = 0; m < 2; ++m) {
            mma_bf16(accA[m][2 * p],     al[m], bh[p]);
            mma_bf16(accA[m][2 * p + 1], al[m], bh[p] + 2);
        }
    #pragma unroll
    for (int p = 0; p < 4; ++p)
        #pragma unroll
        for (int m = 0; m < 2; ++m) {
            mma_bf16(accA[m][2 * p],     ah[m], bl[p]);
            mma_bf16(accA[m][2 * p + 1], ah[m], bl[p] + 2);
        }
}
// K128 sub-stage (layer2)
static __forceinline__ __device__ void compute_k128(
    float accB[2][4][4], const unsigned ah[2][4], const unsigned al[2][4],
    uint32_t brow, uint32_t lo_off, int nq, int lcol8)
{
    unsigned bh[2][4];
    #pragma unroll
    for (int p = 0; p < 2; ++p)
        ldsm4t(bh[p], brow + (uint32_t)(nq * 32 + p * 16 + lcol8) * 2);
    #pragma unroll
    for (int p = 0; p < 2; ++p)
        #pragma unroll
        for (int m = 0; m < 2; ++m) {
            mma_bf16(accB[m][2 * p],     ah[m], bh[p]);
            mma_bf16(accB[m][2 * p + 1], ah[m], bh[p] + 2);
        }
    unsigned bl[2][4];
    #pragma unroll
    for (int p = 0; p < 2; ++p)
        ldsm4t(bl[p], brow + lo_off + (uint32_t)(nq * 32 + p * 16 + lcol8) * 2);
    #pragma unroll
    for (int p = 0; p < 2; ++p)
        #pragma unroll
        for (int m = 0; m < 2; ++m) {
            mma_bf16(accB[m][2 * p],     al[m], bh[p]);
            mma_bf16(accB[m][2 * p + 1], al[m], bh[p] + 2);
        }
    #pragma unroll
    for (int p = 0; p < 2; ++p)
        #pragma unroll
        for (int m = 0; m < 2; ++m) {
            mma_bf16(accB[m][2 * p],     ah[m], bl[p]);
            mma_bf16(accB[m][2 * p + 1], ah[m], bl[p] + 2);
        }
}

// ---------- big-level kernel (levels 17..14) ----------
template<bool LEAF>
__global__ void __launch_bounds__(256, 2)
level_kernel(const float* __restrict__ X, float* __restrict__ Y,
             float* __restrict__ Yemb,
             const float* __restrict__ b1, const float* __restrict__ b2,
             const float* __restrict__ be, int n)
{
    extern __shared__ __align__(16) char sm[];
    const uint32_t base = smem_u32(sm);
    const int tid = threadIdx.x, wid = tid >> 5, lane = tid & 31;
    const int rg = wid >> 2, nq = wid & 3;
    const int wr = rg * 32;
    const int row0 = blockIdx.x * 64;
    const int lrow = lane & 15, lcol8 = (lane >> 4) * 8;
    const int qr = lane >> 2, qc = (lane & 3) * 2;

    constexpr int G = LEAF ? 36 : 32;
    constexpr int EPI1_AT = LEAF ? 20 : 16;

    load_slab<LEAF>(0, base, tid);
    load_slab<LEAF>(1, base, tid);

    ((float*)(sm + SB1))[tid] = b1[tid];
    if (tid < 128) ((float*)(sm + SB2))[tid] = b2[tid];
    if (tid < 128) ((float*)(sm + SBE))[tid] = be[tid];

    if (LEAF) {
        const float* Xb = X + (size_t)row0 * 64;
        for (int idx = tid; idx < 64 * 16; idx += 256) {
            int r = idx >> 4, c4 = idx & 15;
            float4 v = make_float4(0.f, 0.f, 0.f, 0.f);
            if (row0 + r < n) v = reinterpret_cast<const float4*>(Xb)[r * 16 + c4];
            __nv_bfloat162 h0, l0, h1, l1;
            split2(v.x, v.y, h0, l0); split2(v.z, v.w, h1, l1);
            uint32_t off = (uint32_t)r * 528 + c4 * 8;
            *(__nv_bfloat162*)(sm + SA_HI + off)     = h0;
            *(__nv_bfloat162*)(sm + SA_HI + off + 4) = h1;
            *(__nv_bfloat162*)(sm + SA_LO + off)     = l0;
            *(__nv_bfloat162*)(sm + SA_LO + off + 4) = l1;
        }
    } else {
        for (int idx = tid; idx < 64 * 64; idx += 256) {
            int r = idx >> 6, c4 = idx & 63;
            float4 v = make_float4(0.f, 0.f, 0.f, 0.f);
            if (row0 + r < n) v = reinterpret_cast<const float4*>(X)[(size_t)(row0 + r) * 64 + c4];
            __nv_bfloat162 h0, l0, h1, l1;
            split2(v.x, v.y, h0, l0); split2(v.z, v.w, h1, l1);
            uint32_t off = (uint32_t)r * 528 + c4 * 8;
            *(__nv_bfloat162*)(sm + SA_HI + off)     = h0;
            *(__nv_bfloat162*)(sm + SA_HI + off + 4) = h1;
            *(__nv_bfloat162*)(sm + SA_LO + off)     = l0;
            *(__nv_bfloat162*)(sm + SA_LO + off + 4) = l1;
        }
    }
    __syncthreads();

    const float* sB1 = (const float*)(sm + SB1);
    const float* sB2 = (const float*)(sm + SB2);
    const float* sBE = (const float*)(sm + SBE);

    float accA[2][8][4];
    float accB[2][4][4];
    #pragma unroll
    for (int m = 0; m < 2; ++m)
        #pragma unroll
        for (int t = 0; t < 8; ++t) {
            int c = nq * 64 + t * 8 + qc;
            float v0 = LEAF ? sBE[c & 127] : sB1[c];
            float v1 = LEAF ? sBE[(c + 1) & 127] : sB1[c + 1];
            accA[m][t][0] = v0; accA[m][t][1] = v1; accA[m][t][2] = v0; accA[m][t][3] = v1;
        }

    const uint32_t aH0 = base + SA_HI + (uint32_t)(wr + lrow) * 528;
    const uint32_t aH1 = aH0 + 16 * 528;
    const uint32_t aL0 = base + SA_LO + (uint32_t)(wr + lrow) * 528;
    const uint32_t aL1 = aL0 + 16 * 528;

    for (int g = 0; g < G; ++g) {
        if (LEAF && g == 4) {
            #pragma unroll
            for (int m = 0; m < 2; ++m)
                #pragma unroll
                for (int t = 0; t < 8; ++t) {
                    int c = nq * 64 + t * 8 + qc;
                    int r = wr + m * 16 + qr;
                    float v0 = lrelu(accA[m][t][0]), v1 = lrelu(accA[m][t][1]);
                    float v2 = lrelu(accA[m][t][2]), v3 = lrelu(accA[m][t][3]);
                    __nv_bfloat162 hi2, lo2;
                    split2(v0, v1, hi2, lo2);
                    *(__nv_bfloat162*)(sm + SA_HI + r * 528 + c * 2) = hi2;
                    *(__nv_bfloat162*)(sm + SA_LO + r * 528 + c * 2) = lo2;
                    if (row0 + r < n)
                        *reinterpret_cast<float2*>(Yemb + (size_t)(row0 + r) * 256 + c) = make_float2(v0, v1);
                    split2(v2, v3, hi2, lo2);
                    *(__nv_bfloat162*)(sm + SA_HI + (r + 8) * 528 + c * 2) = hi2;
                    *(__nv_bfloat162*)(sm + SA_LO + (r + 8) * 528 + c * 2) = lo2;
                    if (row0 + r + 8 < n)
                        *reinterpret_cast<float2*>(Yemb + (size_t)(row0 + r + 8) * 256 + c) = make_float2(v2, v3);
                }
            #pragma unroll
            for (int m = 0; m < 2; ++m)
                #pragma unroll
                for (int t = 0; t < 8; ++t) {
                    int c = nq * 64 + t * 8 + qc;
                    accA[m][t][0] = sB1[c]; accA[m][t][1] = sB1[c + 1];
                    accA[m][t][2] = sB1[c]; accA[m][t][3] = sB1[c + 1];
                }
        }
        if (g == EPI1_AT) {
            #pragma unroll
            for (int m = 0; m < 2; ++m)
                #pragma unroll
                for (int t = 0; t < 8; ++t) {
                    int c = nq * 64 + t * 8 + qc;
                    int r = wr + m * 16 + qr;
                    __nv_bfloat162 hi2, lo2;
                    split2(lrelu(accA[m][t][0]), lrelu(accA[m][t][1]), hi2, lo2);
                    *(__nv_bfloat162*)(sm + SA_HI + r * 528 + c * 2) = hi2;
                    *(__nv_bfloat162*)(sm + SA_LO + r * 528 + c * 2) = lo2;
                    split2(lrelu(accA[m][t][2]), lrelu(accA[m][t][3]), hi2, lo2);
                    *(__nv_bfloat162*)(sm + SA_HI + (r + 8) * 528 + c * 2) = hi2;
                    *(__nv_bfloat162*)(sm + SA_LO + (r + 8) * 528 + c * 2) = lo2;
                }
            #pragma unroll
            for (int m = 0; m < 2; ++m)
                #pragma unroll
                for (int t = 0; t < 4; ++t) {
                    int c = nq * 32 + t * 8 + qc;
                    accB[m][t][0] = sB2[c]; accB[m][t][1] = sB2[c + 1];
                    accB[m][t][2] = sB2[c]; accB[m][t][3] = sB2[c + 1];
                }
        }

        if (g + 1 < G) { CP_WAIT(1); } else { CP_WAIT(0); }
        __syncthreads();

        int k0;
        if (LEAF) k0 = (g < 4) ? g * 16 : (g < 20 ? (g - 4) * 16 : (g - 20) * 16);
        else      k0 = (g < 16) ? g * 16 : (g - 16) * 16;
        const uint32_t slot = base + W_ST + (uint32_t)(g & 1) * 16896u;

        unsigned ah[2][4], al[2][4];
        ldsm4(ah[0], aH0 + (uint32_t)(k0 + lcol8) * 2);
        ldsm4(ah[1], aH1 + (uint32_t)(k0 + lcol8) * 2);
        ldsm4(al[0], aL0 + (uint32_t)(k0 + lcol8) * 2);
        ldsm4(al[1], aL1 + (uint32_t)(k0 + lcol8) * 2);

        if (g < EPI1_AT) {
            compute_k256(accA, ah, al, slot + (uint32_t)lrow * 528, 8448u, nq, lcol8);
        } else {
            compute_k128(accB, ah, al, slot + (uint32_t)lrow * 272, 4352u, nq, lcol8);
        }
        __syncthreads();
        if (g + 2 < G) load_slab<LEAF>(g + 2, base, tid);
    }

    #pragma unroll
    for (int m = 0; m < 2; ++m)
        #pragma unroll
        for (int t = 0; t < 4; ++t) {
            int c = nq * 32 + t * 8 + qc;
            int r = row0 + wr + m * 16 + qr;
            if (r < n)
                *reinterpret_cast<float2*>(Y + (size_t)r * 128 + c) =
                    make_float2(lrelu(accB[m][t][0]), lrelu(accB[m][t][1]));
            if (r + 8 < n)
                *reinterpret_cast<float2*>(Y + (size_t)(r + 8) * 128 + c) =
                    make_float2(lrelu(accB[m][t][2]), lrelu(accB[m][t][3]));
        }
}

// small levels 13..7: one level per launch, 8 stages, K-slab 64.
__global__ void __launch_bounds__(256, 1)
small_kernel(const float* __restrict__ X, float* __restrict__ Y,
             const float* __restrict__ b1, const float* __restrict__ b2, int n)
{
    extern __shared__ __align__(16) char sm[];
    const uint32_t base = smem_u32(sm);
    const int tid = threadIdx.x, wid = tid >> 5, lane = tid & 31;
    const int rg = wid >> 2, nq = wid & 3;
    const int wr = rg * 32;
    const int row0 = blockIdx.x * 64;
    const int lrow = lane & 15, lcol8 = (lane >> 4) * 8;
    const int qr = lane >> 2, qc = (lane & 3) * 2;
    const uint32_t wbase = base + S_W;

    load_slab64(0, wbase, tid);
    load_slab64(1, wbase, tid);

    ((float*)(sm + S_SB1))[tid] = b1[tid];
    if (tid < 128) ((float*)(sm + S_SB2))[tid] = b2[tid];

    for (int idx = tid; idx < 64 * 64; idx += 256) {
        int r = idx >> 6, c4 = idx & 63;
        float4 v = make_float4(0.f, 0.f, 0.f, 0.f);
        if (row0 + r < n) v = reinterpret_cast<const float4*>(X)[(size_t)(row0 + r) * 64 + c4];
        __nv_bfloat162 h0, l0, h1, l1;
        split2(v.x, v.y, h0, l0); split2(v.z, v.w, h1, l1);
        uint32_t off = (uint32_t)r * 528 + c4 * 8;
        *(__nv_bfloat162*)(sm + SA_HI + off)     = h0;
        *(__nv_bfloat162*)(sm + SA_HI + off + 4) = h1;
        *(__nv_bfloat162*)(sm + SA_LO + off)     = l0;
        *(__nv_bfloat162*)(sm + SA_LO + off + 4) = l1;
    }
    __syncthreads();

    const float* sB1 = (const float*)(sm + S_SB1);
    const float* sB2 = (const float*)(sm + S_SB2);

    float accA[2][8][4], accB[2][4][4];
    #pragma unroll
    for (int m = 0; m < 2; ++m)
        #pragma unroll
        for (int t = 0; t < 8; ++t) {
            int c = nq * 64 + t * 8 + qc;
            accA[m][t][0] = sB1[c]; accA[m][t][1] = sB1[c + 1];
            accA[m][t][2] = sB1[c]; accA[m][t][3] = sB1[c + 1];
        }

    const uint32_t aH0 = base + SA_HI + (uint32_t)(wr + lrow) * 528;
    const uint32_t aH1 = aH0 + 16 * 528;
    const uint32_t aL0 = base + SA_LO + (uint32_t)(wr + lrow) * 528;
    const uint32_t aL1 = aL0 + 16 * 528;

    for (int g = 0; g < 8; ++g) {
        if (g == 4) {
            #pragma unroll
            for (int m = 0; m < 2; ++m)
                #pragma unroll
                for (int t = 0; t < 8; ++t) {
                    int c = nq * 64 + t * 8 + qc;
                    int r = wr + m * 16 + qr;
                    __nv_bfloat162 hi2, lo2;
                    split2(lrelu(accA[m][t][0]), lrelu(accA[m][t][1]), hi2, lo2);
                    *(__nv_bfloat162*)(sm + SA_HI + r * 528 + c * 2) = hi2;
                    *(__nv_bfloat162*)(sm + SA_LO + r * 528 + c * 2) = lo2;
                    split2(lrelu(accA[m][t][2]), lrelu(accA[m][t][3]), hi2, lo2);
                    *(__nv_bfloat162*)(sm + SA_HI + (r + 8) * 528 + c * 2) = hi2;
                    *(__nv_bfloat162*)(sm + SA_LO + (r + 8) * 528 + c * 2) = lo2;
                }
            #pragma unroll
            for (int m = 0; m < 2; ++m)
                #pragma unroll
                for (int t = 0; t < 4; ++t) {
                    int c = nq * 32 + t * 8 + qc;
                    accB[m][t][0] = sB2[c]; accB[m][t][1] = sB2[c + 1];
                    accB[m][t][2] = sB2[c]; accB[m][t][3] = sB2[c + 1];
                }
        }

        if (g + 1 < 8) { CP_WAIT(1); } else { CP_WAIT(0); }
        __syncthreads();

        const uint32_t slot = wbase + (uint32_t)(g & 1) * 67584u;
        const int kb = (g < 4 ? g : g - 4) * 64;

        #pragma unroll
        for (int j = 0; j < 4; ++j) {
            const int k0 = kb + j * 16;
            unsigned ah[2][4], al[2][4];
            ldsm4(ah[0], aH0 + (uint32_t)(k0 + lcol8) * 2);
            ldsm4(ah[1], aH1 + (uint32_t)(k0 + lcol8) * 2);
            ldsm4(al[0], aL0 + (uint32_t)(k0 + lcol8) * 2);
            ldsm4(al[1], aL1 + (uint32_t)(k0 + lcol8) * 2);
            if (g < 4) {
                compute_k256(accA, ah, al, slot + (uint32_t)(j * 16 + lrow) * 528, 33792u, nq, lcol8);
            } else {
                compute_k128(accB, ah, al, slot + (uint32_t)(j * 16 + lrow) * 272, 17408u, nq, lcol8);
            }
        }
        __syncthreads();
        if (g + 2 < 8) load_slab64(g + 2, wbase, tid);
    }

    #pragma unroll
    for (int m = 0; m < 2; ++m)
        #pragma unroll
        for (int t = 0; t < 4; ++t) {
            int c = nq * 32 + t * 8 + qc;
            int r = row0 + wr + m * 16 + qr;
            if (r < n)
                *reinterpret_cast<float2*>(Y + (size_t)r * 128 + c) =
                    make_float2(lrelu(accB[m][t][0]), lrelu(accB[m][t][1]));
            if (r + 8 < n)
                *reinterpret_cast<float2*>(Y + (size_t)(r + 8) * 128 + c) =
                    make_float2(lrelu(accB[m][t][2]), lrelu(accB[m][t][3]));
        }
}

// tail: levels 6..0 in one CTA, 56 stages, K-slab 64.
__global__ void __launch_bounds__(256, 1)
tail_kernel(float* __restrict__ out,
            const float* __restrict__ b1, const float* __restrict__ b2)
{
    extern __shared__ __align__(16) char sm[];
    const uint32_t base = smem_u32(sm);
    const int tid = threadIdx.x, wid = tid >> 5, lane = tid & 31;
    const int rg = wid >> 2, nq = wid & 3;
    const int wr = rg * 32;
    const int lrow = lane & 15, lcol8 = (lane >> 4) * 8;
    const int qr = lane >> 2, qc = (lane & 3) * 2;
    const uint32_t wbase = base + S_W;

    load_slab64(0, wbase, tid);
    load_slab64(1, wbase, tid);

    ((float*)(sm + S_SB1))[tid] = b1[tid];
    if (tid < 128) ((float*)(sm + S_SB2))[tid] = b2[tid];

    {
        const float* X = out + 127 * 128;
        for (int idx = tid; idx < 64 * 64; idx += 256) {
            int r = idx >> 6, c4 = idx & 63;
            float4 v = reinterpret_cast<const float4*>(X)[r * 64 + c4];
            __nv_bfloat162 h0, l0, h1, l1;
            split2(v.x, v.y, h0, l0); split2(v.z, v.w, h1, l1);
            uint32_t off = (uint32_t)r * 528 + c4 * 8;
            *(__nv_bfloat162*)(sm + SA_HI + off)     = h0;
            *(__nv_bfloat162*)(sm + SA_HI + off + 4) = h1;
            *(__nv_bfloat162*)(sm + SA_LO + off)     = l0;
            *(__nv_bfloat162*)(sm + SA_LO + off + 4) = l1;
        }
    }
    __syncthreads();

    const float* sB1 = (const float*)(sm + S_SB1);
    const float* sB2 = (const float*)(sm + S_SB2);

    float accA[2][8][4], accB[2][4][4];
    #pragma unroll
    for (int m = 0; m < 2; ++m)
        #pragma unroll
        for (int t = 0; t < 8; ++t) {
            int c = nq * 64 + t * 8 + qc;
            accA[m][t][0] = sB1[c]; accA[m][t][1] = sB1[c + 1];
            accA[m][t][2] = sB1[c]; accA[m][t][3] = sB1[c + 1];
        }

    const uint32_t aH0 = base + SA_HI + (uint32_t)(wr + lrow) * 528;
    const uint32_t aH1 = aH0 + 16 * 528;
    const uint32_t aL0 = base + SA_LO + (uint32_t)(wr + lrow) * 528;
    const uint32_t aL1 = aL0 + 16 * 528;

    int n = 64;
    constexpr int GT = 7 * 8;
    for (int g = 0; g < GT; ++g) {
        const int ph = g & 7;
        if (ph == 0 && g > 0) {
            const int lvDone = 7 - (g >> 3);
            float* Y = out + (((size_t)1 << lvDone) - 1) * 128;
            #pragma unroll
            for (int m = 0; m < 2; ++m)
                #pragma unroll
                for (int t = 0; t < 4; ++t) {
                    int c = nq * 32 + t * 8 + qc;
                    #pragma unroll
                    for (int h = 0; h < 2; ++h) {
                        int r = wr + m * 16 + qr + h * 8;
                        float v0 = lrelu(accB[m][t][2 * h]);
                        float v1 = lrelu(accB[m][t][2 * h + 1]);
                        if (r < n)
                            *reinterpret_cast<float2*>(Y + (size_t)r * 128 + c) = make_float2(v0, v1);
                        __nv_bfloat162 hi2, lo2;
                        split2(v0, v1, hi2, lo2);
                        uint32_t off = (uint32_t)(r >> 1) * 528 + ((r & 1) * 128 + c) * 2;
                        *(__nv_bfloat162*)(sm + SA_HI + off) = hi2;
                        *(__nv_bfloat162*)(sm + SA_LO + off) = lo2;
                    }
                }
            #pragma unroll
            for (int m = 0; m < 2; ++m)
                #pragma unroll
                for (int t = 0; t < 8; ++t) {
                    int c = nq * 64 + t * 8 + qc;
                    accA[m][t][0] = sB1[c]; accA[m][t][1] = sB1[c + 1];
                    accA[m][t][2] = sB1[c]; accA[m][t][3] = sB1[c + 1];
                }
            n >>= 1;
        }
        if (ph == 4) {
            #pragma unroll
            for (int m = 0; m < 2; ++m)
                #pragma unroll
                for (int t = 0; t < 8; ++t) {
                    int c = nq * 64 + t * 8 + qc;
                    int r = wr + m * 16 + qr;
                    __nv_bfloat162 hi2, lo2;
                    split2(lrelu(accA[m][t][0]), lrelu(accA[m][t][1]), hi2, lo2);
                    *(__nv_bfloat162*)(sm + SA_HI + r * 528 + c * 2) = hi2;
                    *(__nv_bfloat162*)(sm + SA_LO + r * 528 + c * 2) = lo2;
                    split2(lrelu(accA[m][t][2]), lrelu(accA[m][t][3]), hi2, lo2);
                    *(__nv_bfloat162*)(sm + SA_HI + (r + 8) * 528 + c * 2) = hi2;
                    *(__nv_bfloat162*)(sm + SA_LO + (r + 8) * 528 + c * 2) = lo2;
                }
            #pragma unroll
            for (int m = 0; m < 2; ++m)
                #pragma unroll
                for (int t = 0; t < 4; ++t) {
                    int c = nq * 32 + t * 8 + qc;
                    accB[m][t][0] = sB2[c]; accB[m][t][1] = sB2[c + 1];
                    accB[m][t][2] = sB2[c]; accB[m][t][3] = sB2[c + 1];
                }
        }

        if (g + 1 < GT) { CP_WAIT(1); } else { CP_WAIT(0); }
        __syncthreads();

        const uint32_t slot = wbase + (uint32_t)(g & 1) * 67584u;
        const int kb = (ph < 4 ? ph : ph - 4) * 64;

        #pragma unroll
        for (int j = 0; j < 4; ++j) {
            const int k0 = kb + j * 16;
            unsigned ah[2][4], al[2][4];
            ldsm4(ah[0], aH0 + (uint32_t)(k0 + lcol8) * 2);
            ldsm4(ah[1], aH1 + (uint32_t)(k0 + lcol8) * 2);
            ldsm4(al[0], aL0 + (uint32_t)(k0 + lcol8) * 2);
            ldsm4(al[1], aL1 + (uint32_t)(k0 + lcol8) * 2);
            if (ph < 4) {
                compute_k256(accA, ah, al, slot + (uint32_t)(j * 16 + lrow) * 528, 33792u, nq, lcol8);
            } else {
                compute_k128(accB, ah, al, slot + (uint32_t)(j * 16 + lrow) * 272, 17408u, nq, lcol8);
            }
        }
        __syncthreads();
        if (g + 2 < GT) load_slab64((g + 2) & 7, wbase, tid);
    }

    #pragma unroll
    for (int m = 0; m < 2; ++m)
        #pragma unroll
        for (int t = 0; t < 4; ++t) {
            int c = nq * 32 + t * 8 + qc;
            #pragma unroll
            for (int h = 0; h < 2; ++h) {
                int r = wr + m * 16 + qr + h * 8;
                if (r < 1)
                    *reinterpret_cast<float2*>(out + (size_t)r * 128 + c) =
                        make_float2(lrelu(accB[m][t][2 * h]), lrelu(accB[m][t][2 * h + 1]));
            }
        }
}

extern "C" void kernel_launch(void* const* d_in, const int* in_sizes, int n_in,
                              void* d_out, int out_size)
{
    const float* leaf = (const float*)d_in[0];
    const float* We   = (const float*)d_in[1];
    const float* be   = (const float*)d_in[2];
    const float* W1   = (const float*)d_in[3];
    const float* b1   = (const float*)d_in[4];
    const float* W2   = (const float*)d_in[5];
    const float* b2   = (const float*)d_in[6];
    float* out = (float*)d_out;

    cudaFuncSetAttribute(level_kernel<true>,  cudaFuncAttributeMaxDynamicSharedMemorySize, SMEM_LVL);
    cudaFuncSetAttribute(level_kernel<false>, cudaFuncAttributeMaxDynamicSharedMemorySize, SMEM_LVL);
    cudaFuncSetAttribute(small_kernel, cudaFuncAttributeMaxDynamicSharedMemorySize, SMEM_SMALL);
    cudaFuncSetAttribute(tail_kernel,  cudaFuncAttributeMaxDynamicSharedMemorySize, SMEM_SMALL);

    prep_kernel<<<256, 256>>>(W1, W2, We);

    const size_t leaf_start = (size_t)(1u << DEPTH) - 1;
    float* Yemb = out + leaf_start * 128;

    for (int l = DEPTH - 1; l >= 7; --l) {
        const int n = 1 << l;
        const size_t p0 = (size_t)(1u << l) - 1;
        float* Y = out + p0 * 128;
        const int grid = (n + 63) / 64;
        if (l == DEPTH - 1) {
            level_kernel<true><<<grid, 256, SMEM_LVL>>>(leaf, Y, Yemb, b1, b2, be, n);
        } else if (l >= 14) {
            const float* X = out + (2 * p0 + 1) * 128;
            level_kernel<false><<<grid, 256, SMEM_LVL>>>(X, Y, Yemb, b1, b2, be, n);
        } else {
            const float* X = out + (2 * p0 + 1) * 128;
            small_kernel<<<grid, 256, SMEM_SMALL>>>(X, Y, b1, b2, n);
        }
    }
    tail_kernel<<<1, 256, SMEM_SMALL>>>(out, b1, b2);
}

// round 14
// speedup vs baseline: 1.0119x; 1.0119x over previous
#include <cuda_runtime.h>
#include <cuda_bf16.h>
#include <cstdint>

// R14: revert compute core to R5's 16x128 warp tiling (measured 49% tensor,
// 1.17us/stage-wave vs 1.51 for 32x64), applied to big-level, small (slab64)
// and tail kernels. Keeps: fused leaf embedder, slab64 small levels, 56-stage
// tail, deep cp.async pipeline.

static __forceinline__ __device__ float lrelu(float v) { return v > 0.0f ? v : 0.01f * v; }

constexpr int DEPTH = 18;
// big-level kernel smem map
constexpr int SA_HI = 0;        // [64][528B] bf16
constexpr int SA_LO = 33792;
constexpr int W_ST  = 67584;    // 2 slots x 16896
constexpr int SB1   = 101376;
constexpr int SB2   = 102400;
constexpr int SBE   = 102912;
constexpr int SMEM_LVL = 103424;

// slab64 kernels smem map
constexpr int S_W   = 67584;              // 2 slots x 67584
constexpr int S_SB1 = 202752;
constexpr int S_SB2 = 203776;
constexpr int SMEM_SMALL = 204288;

// prepped split weights (row-major bf16)
__device__ __align__(16) __nv_bfloat16 W1hi_d[65536];   // [256][256]
__device__ __align__(16) __nv_bfloat16 W1lo_d[65536];
__device__ __align__(16) __nv_bfloat16 W2hi_d[32768];   // [256][128]
__device__ __align__(16) __nv_bfloat16 W2lo_d[32768];
__device__ __align__(16) __nv_bfloat16 WBhi_d[16384];   // blockdiag(We,We) [64][256]
__device__ __align__(16) __nv_bfloat16 WBlo_d[16384];

static __forceinline__ __device__ uint32_t smem_u32(const void* p) {
    uint32_t a;
    asm("{ .reg .u64 t; cvta.to.shared.u64 t, %1; cvt.u32.u64 %0, t; }" : "=r"(a) : "l"(p));
    return a;
}
static __forceinline__ __device__ void cp16(uint32_t d, const void* s) {
    asm volatile("cp.async.cg.shared.global [%0], [%1], 16;" :: "r"(d), "l"(s));
}
#define CP_COMMIT() asm volatile("cp.async.commit_group;" ::: "memory")
#define CP_WAIT(N)  asm volatile("cp.async.wait_group %0;" :: "n"(N) : "memory")

static __forceinline__ __device__ void ldsm4(unsigned* r, uint32_t a) {
    asm volatile("ldmatrix.sync.aligned.m8n8.x4.shared.b16 {%0,%1,%2,%3}, [%4];"
                 : "=r"(r[0]), "=r"(r[1]), "=r"(r[2]), "=r"(r[3]) : "r"(a));
}
static __forceinline__ __device__ void ldsm4t(unsigned* r, uint32_t a) {
    asm volatile("ldmatrix.sync.aligned.m8n8.x4.trans.shared.b16 {%0,%1,%2,%3}, [%4];"
                 : "=r"(r[0]), "=r"(r[1]), "=r"(r[2]), "=r"(r[3]) : "r"(a));
}
static __forceinline__ __device__ void mma_bf16(float* c, const unsigned* a, const unsigned* b) {
    asm volatile("mma.sync.aligned.m16n8k16.row.col.f32.bf16.bf16.f32 "
                 "{%0,%1,%2,%3}, {%4,%5,%6,%7}, {%8,%9}, {%0,%1,%2,%3};"
                 : "+f"(c[0]), "+f"(c[1]), "+f"(c[2]), "+f"(c[3])
                 : "r"(a[0]), "r"(a[1]), "r"(a[2]), "r"(a[3]), "r"(b[0]), "r"(b[1]));
}
static __forceinline__ __device__ void split2(float h0, float h1,
                                              __nv_bfloat162& hi, __nv_bfloat162& lo) {
    hi = __floats2bfloat162_rn(h0, h1);
    lo = __floats2bfloat162_rn(h0 - __bfloat162float(hi.x), h1 - __bfloat162float(hi.y));
}

__global__ void prep_kernel(const float* __restrict__ W1, const float* __restrict__ W2,
                            const float* __restrict__ We) {
    int t = blockIdx.x * 256 + threadIdx.x;
    if (t < 65536) {
        float f = W1[t];
        __nv_bfloat16 hi = __float2bfloat16(f);
        W1hi_d[t] = hi; W1lo_d[t] = __float2bfloat16(f - __bfloat162float(hi));
    }
    if (t < 32768) {
        float f = W2[t];
        __nv_bfloat16 hi = __float2bfloat16(f);
        W2hi_d[t] = hi; W2lo_d[t] = __float2bfloat16(f - __bfloat162float(hi));
    }
    if (t < 16384) {
        int k = t >> 8, c = t & 255;
        float f = 0.0f;
        if (k < 32 && c < 128)   f = We[k * 128 + c];
        if (k >= 32 && c >= 128) f = We[(k - 32) * 128 + (c - 128)];
        __nv_bfloat16 hi = __float2bfloat16(f);
        WBhi_d[t] = hi; WBlo_d[t] = __float2bfloat16(f - __bfloat162float(hi));
    }
}

// ---------- big-level slab loader (16 k-rows) ----------
template<bool LEAF>
static __forceinline__ __device__ void load_slab(int g, uint32_t base, int tid) {
    uint32_t slot = base + W_ST + (uint32_t)(g & 1) * 16896u;
    const char *hi, *lo;
    bool k256;
    if (LEAF) {
        if (g < 4)       { hi = (const char*)WBhi_d + (size_t)g * 8192;        lo = (const char*)WBlo_d + (size_t)g * 8192;        k256 = true; }
        else if (g < 20) { hi = (const char*)W1hi_d + (size_t)(g - 4) * 8192;  lo = (const char*)W1lo_d + (size_t)(g - 4) * 8192;  k256 = true; }
        else             { hi = (const char*)W2hi_d + (size_t)(g - 20) * 4096; lo = (const char*)W2lo_d + (size_t)(g - 20) * 4096; k256 = false; }
    } else {
        if (g < 16)      { hi = (const char*)W1hi_d + (size_t)g * 8192;        lo = (const char*)W1lo_d + (size_t)g * 8192;        k256 = true; }
        else             { hi = (const char*)W2hi_d + (size_t)(g - 16) * 4096; lo = (const char*)W2lo_d + (size_t)(g - 16) * 4096; k256 = false; }
    }
    if (k256) {
        #pragma unroll
        for (int j = 0; j < 4; ++j) {
            int idx = tid + j * 256;
            int part = idx >> 9, rc = idx & 511, r = rc >> 5, c = rc & 31;
            cp16(slot + part * 8448 + r * 528 + c * 16, (part ? lo : hi) + r * 512 + c * 16);
        }
    } else {
        #pragma unroll
        for (int j = 0; j < 2; ++j) {
            int idx = tid + j * 256;
            int part = idx >> 8, rc = idx & 255, r = rc >> 4, c = rc & 15;
            cp16(slot + part * 4352 + r * 272 + c * 16, (part ? lo : hi) + r * 256 + c * 16);
        }
    }
    CP_COMMIT();
}

// ---------- slab64 loader: g 0..3 -> W1 64-row slabs, 4..7 -> W2 ----------
static __forceinline__ __device__ void load_slab64(int g, uint32_t wbase, int tid) {
    uint32_t slot = wbase + (uint32_t)(g & 1) * 67584u;
    if (g < 4) {
        const char* hi = (const char*)W1hi_d + (size_t)g * 32768;
        const char* lo = (const char*)W1lo_d + (size_t)g * 32768;
        #pragma unroll
        for (int j = 0; j < 16; ++j) {
            int idx = tid + j * 256;
            int part = idx >> 11, rc = idx & 2047, r = rc >> 5, c = rc & 31;
            cp16(slot + part * 33792 + r * 528 + c * 16, (part ? lo : hi) + r * 512 + c * 16);
        }
    } else {
        const char* hi = (const char*)W2hi_d + (size_t)(g - 4) * 16384;
        const char* lo = (const char*)W2lo_d + (size_t)(g - 4) * 16384;
        #pragma unroll
        for (int j = 0; j < 8; ++j) {
            int idx = tid + j * 256;
            int part = idx >> 10, rc = idx & 1023, r = rc >> 4, c = rc & 15;
            cp16(slot + part * 17408 + r * 272 + c * 16, (part ? lo : hi) + r * 256 + c * 16);
        }
    }
    CP_COMMIT();
}

// ---------- R5-style compute sub-stages (16x128 warp tile) ----------
// K256 (layer1/emb): acc1[16][4], A frags for rows wr..wr+16, B cols nh*128..+128
static __forceinline__ __device__ void compute_k256(
    float acc1[16][4], const unsigned ahi[4], const unsigned alo[4],
    uint32_t brow, uint32_t lo_off, int nh, int lcol8)
{
    #pragma unroll
    for (int p = 0; p < 8; ++p) {
        int nb = nh * 128 + p * 16;
        unsigned bh[4], bl[4];
        ldsm4t(bh, brow + (uint32_t)(nb + lcol8) * 2);
        ldsm4t(bl, brow + lo_off + (uint32_t)(nb + lcol8) * 2);
        mma_bf16(acc1[2 * p],     ahi, bh);
        mma_bf16(acc1[2 * p + 1], ahi, bh + 2);
        mma_bf16(acc1[2 * p],     alo, bh);
        mma_bf16(acc1[2 * p + 1], alo, bh + 2);
        mma_bf16(acc1[2 * p],     ahi, bl);
        mma_bf16(acc1[2 * p + 1], ahi, bl + 2);
    }
}
// K128 (layer2): acc2[8][4], B cols nh*64..+64
static __forceinline__ __device__ void compute_k128(
    float acc2[8][4], const unsigned ahi[4], const unsigned alo[4],
    uint32_t brow, uint32_t lo_off, int nh, int lcol8)
{
    #pragma unroll
    for (int p = 0; p < 4; ++p) {
        int nb = nh * 64 + p * 16;
        unsigned bh[4], bl[4];
        ldsm4t(bh, brow + (uint32_t)(nb + lcol8) * 2);
        ldsm4t(bl, brow + lo_off + (uint32_t)(nb + lcol8) * 2);
        mma_bf16(acc2[2 * p],     ahi, bh);
        mma_bf16(acc2[2 * p + 1], ahi, bh + 2);
        mma_bf16(acc2[2 * p],     alo, bh);
        mma_bf16(acc2[2 * p + 1], alo, bh + 2);
        mma_bf16(acc2[2 * p],     ahi, bl);
        mma_bf16(acc2[2 * p + 1], ahi, bl + 2);
    }
}

// ---------- big-level kernel (levels 17..14) ----------
template<bool LEAF>
__global__ void __launch_bounds__(256, 2)
level_kernel(const float* __restrict__ X, float* __restrict__ Y,
             float* __restrict__ Yemb,
             const float* __restrict__ b1, const float* __restrict__ b2,
             const float* __restrict__ be, int n)
{
    extern __shared__ __align__(16) char sm[];
    const uint32_t base = smem_u32(sm);
    const int tid = threadIdx.x, wid = tid >> 5, lane = tid & 31;
    const int wr = (wid & 3) * 16;              // row group (4 groups of 16)
    const int nh = wid >> 2;                    // n-half (0/1)
    const int row0 = blockIdx.x * 64;
    const int lrow = lane & 15, lcol8 = (lane >> 4) * 8;
    const int qr = lane >> 2, qc = (lane & 3) * 2;

    constexpr int G = LEAF ? 36 : 32;
    constexpr int EPI1_AT = LEAF ? 20 : 16;

    load_slab<LEAF>(0, base, tid);
    load_slab<LEAF>(1, base, tid);

    ((float*)(sm + SB1))[tid] = b1[tid];
    if (tid < 128) ((float*)(sm + SB2))[tid] = b2[tid];
    if (tid < 128) ((float*)(sm + SBE))[tid] = be[tid];

    if (LEAF) {
        const float* Xb = X + (size_t)row0 * 64;
        for (int idx = tid; idx < 64 * 16; idx += 256) {
            int r = idx >> 4, c4 = idx & 15;
            float4 v = make_float4(0.f, 0.f, 0.f, 0.f);
            if (row0 + r < n) v = reinterpret_cast<const float4*>(Xb)[r * 16 + c4];
            __nv_bfloat162 h0, l0, h1, l1;
            split2(v.x, v.y, h0, l0); split2(v.z, v.w, h1, l1);
            uint32_t off = (uint32_t)r * 528 + c4 * 8;
            *(__nv_bfloat162*)(sm + SA_HI + off)     = h0;
            *(__nv_bfloat162*)(sm + SA_HI + off + 4) = h1;
            *(__nv_bfloat162*)(sm + SA_LO + off)     = l0;
            *(__nv_bfloat162*)(sm + SA_LO + off + 4) = l1;
        }
    } else {
        for (int idx = tid; idx < 64 * 64; idx += 256) {
            int r = idx >> 6, c4 = idx & 63;
            float4 v = make_float4(0.f, 0.f, 0.f, 0.f);
            if (row0 + r < n) v = reinterpret_cast<const float4*>(X)[(size_t)(row0 + r) * 64 + c4];
            __nv_bfloat162 h0, l0, h1, l1;
            split2(v.x, v.y, h0, l0); split2(v.z, v.w, h1, l1);
            uint32_t off = (uint32_t)r * 528 + c4 * 8;
            *(__nv_bfloat162*)(sm + SA_HI + off)     = h0;
            *(__nv_bfloat162*)(sm + SA_HI + off + 4) = h1;
            *(__nv_bfloat162*)(sm + SA_LO + off)     = l0;
            *(__nv_bfloat162*)(sm + SA_LO + off + 4) = l1;
        }
    }
    __syncthreads();

    const float* sB1 = (const float*)(sm + SB1);
    const float* sB2 = (const float*)(sm + SB2);
    const float* sBE = (const float*)(sm + SBE);

    float acc1[16][4];   // emb(leaf)/layer1: warp 16 x 128 (cols nh*128..)
    float acc2[8][4];    // layer2: warp 16 x 64 (cols nh*64..)
    #pragma unroll
    for (int t = 0; t < 16; ++t) {
        int c = nh * 128 + t * 8 + qc;
        float v0 = LEAF ? sBE[c & 127] : sB1[c];
        float v1 = LEAF ? sBE[(c + 1) & 127] : sB1[c + 1];
        acc1[t][0] = v0; acc1[t][1] = v1; acc1[t][2] = v0; acc1[t][3] = v1;
    }

    const uint32_t aHi = base + SA_HI + (uint32_t)(wr + lrow) * 528;
    const uint32_t aLo = base + SA_LO + (uint32_t)(wr + lrow) * 528;

    for (int g = 0; g < G; ++g) {
        if (LEAF && g == 4) {
            // emb epilogue: acc1 -> lrelu -> gmem leaf slab + split back into sA
            #pragma unroll
            for (int t = 0; t < 16; ++t) {
                int c = nh * 128 + t * 8 + qc;
                float v0 = lrelu(acc1[t][0]), v1 = lrelu(acc1[t][1]);
                float v2 = lrelu(acc1[t][2]), v3 = lrelu(acc1[t][3]);
                __nv_bfloat162 hi2, lo2;
                split2(v0, v1, hi2, lo2);
                uint32_t o0 = (uint32_t)(wr + qr) * 528 + c * 2;
                *(__nv_bfloat162*)(sm + SA_HI + o0) = hi2;
                *(__nv_bfloat162*)(sm + SA_LO + o0) = lo2;
                if (row0 + wr + qr < n)
                    *reinterpret_cast<float2*>(Yemb + (size_t)(row0 + wr + qr) * 256 + c) = make_float2(v0, v1);
                split2(v2, v3, hi2, lo2);
                uint32_t o1 = (uint32_t)(wr + qr + 8) * 528 + c * 2;
                *(__nv_bfloat162*)(sm + SA_HI + o1) = hi2;
                *(__nv_bfloat162*)(sm + SA_LO + o1) = lo2;
                if (row0 + wr + qr + 8 < n)
                    *reinterpret_cast<float2*>(Yemb + (size_t)(row0 + wr + qr + 8) * 256 + c) = make_float2(v2, v3);
            }
            #pragma unroll
            for (int t = 0; t < 16; ++t) {
                int c = nh * 128 + t * 8 + qc;
                acc1[t][0] = sB1[c]; acc1[t][1] = sB1[c + 1];
                acc1[t][2] = sB1[c]; acc1[t][3] = sB1[c + 1];
            }
        }
        if (g == EPI1_AT) {
            // layer-1 epilogue: acc1 -> H (lrelu, split) into sA; init acc2
            #pragma unroll
            for (int t = 0; t < 16; ++t) {
                int c = nh * 128 + t * 8 + qc;
                __nv_bfloat162 hi2, lo2;
                split2(lrelu(acc1[t][0]), lrelu(acc1[t][1]), hi2, lo2);
                uint32_t o0 = (uint32_t)(wr + qr) * 528 + c * 2;
                *(__nv_bfloat162*)(sm + SA_HI + o0) = hi2;
                *(__nv_bfloat162*)(sm + SA_LO + o0) = lo2;
                split2(lrelu(acc1[t][2]), lrelu(acc1[t][3]), hi2, lo2);
                uint32_t o1 = (uint32_t)(wr + qr + 8) * 528 + c * 2;
                *(__nv_bfloat162*)(sm + SA_HI + o1) = hi2;
                *(__nv_bfloat162*)(sm + SA_LO + o1) = lo2;
            }
            #pragma unroll
            for (int t = 0; t < 8; ++t) {
                int c = nh * 64 + t * 8 + qc;
                acc2[t][0] = sB2[c]; acc2[t][1] = sB2[c + 1];
                acc2[t][2] = sB2[c]; acc2[t][3] = sB2[c + 1];
            }
        }

        if (g + 1 < G) { CP_WAIT(1); } else { CP_WAIT(0); }
        __syncthreads();

        int k0;
        if (LEAF) k0 = (g < 4) ? g * 16 : (g < 20 ? (g - 4) * 16 : (g - 20) * 16);
        else      k0 = (g < 16) ? g * 16 : (g - 16) * 16;
        const uint32_t slot = base + W_ST + (uint32_t)(g & 1) * 16896u;

        unsigned ahi[4], alo[4];
        ldsm4(ahi, aHi + (uint32_t)(k0 + lcol8) * 2);
        ldsm4(alo, aLo + (uint32_t)(k0 + lcol8) * 2);

        if (g < EPI1_AT) {
            compute_k256(acc1, ahi, alo, slot + (uint32_t)lrow * 528, 8448u, nh, lcol8);
        } else {
            compute_k128(acc2, ahi, alo, slot + (uint32_t)lrow * 272, 4352u, nh, lcol8);
        }
        __syncthreads();
        if (g + 2 < G) load_slab<LEAF>(g + 2, base, tid);
    }

    // final epilogue: Y = lrelu(acc2)
    #pragma unroll
    for (int t = 0; t < 8; ++t) {
        int c = nh * 64 + t * 8 + qc;
        int r = row0 + wr + qr;
        if (r < n)
            *reinterpret_cast<float2*>(Y + (size_t)r * 128 + c) =
                make_float2(lrelu(acc2[t][0]), lrelu(acc2[t][1]));
        if (r + 8 < n)
            *reinterpret_cast<float2*>(Y + (size_t)(r + 8) * 128 + c) =
                make_float2(lrelu(acc2[t][2]), lrelu(acc2[t][3]));
    }
}

// small levels 13..7: one level per launch, 8 stages, K-slab 64.
__global__ void __launch_bounds__(256, 1)
small_kernel(const float* __restrict__ X, float* __restrict__ Y,
             const float* __restrict__ b1, const float* __restrict__ b2, int n)
{
    extern __shared__ __align__(16) char sm[];
    const uint32_t base = smem_u32(sm);
    const int tid = threadIdx.x, wid = tid >> 5, lane = tid & 31;
    const int wr = (wid & 3) * 16, nh = wid >> 2;
    const int row0 = blockIdx.x * 64;
    const int lrow = lane & 15, lcol8 = (lane >> 4) * 8;
    const int qr = lane >> 2, qc = (lane & 3) * 2;
    const uint32_t wbase = base + S_W;

    load_slab64(0, wbase, tid);
    load_slab64(1, wbase, tid);

    ((float*)(sm + S_SB1))[tid] = b1[tid];
    if (tid < 128) ((float*)(sm + S_SB2))[tid] = b2[tid];

    for (int idx = tid; idx < 64 * 64; idx += 256) {
        int r = idx >> 6, c4 = idx & 63;
        float4 v = make_float4(0.f, 0.f, 0.f, 0.f);
        if (row0 + r < n) v = reinterpret_cast<const float4*>(X)[(size_t)(row0 + r) * 64 + c4];
        __nv_bfloat162 h0, l0, h1, l1;
        split2(v.x, v.y, h0, l0); split2(v.z, v.w, h1, l1);
        uint32_t off = (uint32_t)r * 528 + c4 * 8;
        *(__nv_bfloat162*)(sm + SA_HI + off)     = h0;
        *(__nv_bfloat162*)(sm + SA_HI + off + 4) = h1;
        *(__nv_bfloat162*)(sm + SA_LO + off)     = l0;
        *(__nv_bfloat162*)(sm + SA_LO + off + 4) = l1;
    }
    __syncthreads();

    const float* sB1 = (const float*)(sm + S_SB1);
    const float* sB2 = (const float*)(sm + S_SB2);

    float acc1[16][4], acc2[8][4];
    #pragma unroll
    for (int t = 0; t < 16; ++t) {
        int c = nh * 128 + t * 8 + qc;
        acc1[t][0] = sB1[c]; acc1[t][1] = sB1[c + 1];
        acc1[t][2] = sB1[c]; acc1[t][3] = sB1[c + 1];
    }

    const uint32_t aHi = base + SA_HI + (uint32_t)(wr + lrow) * 528;
    const uint32_t aLo = base + SA_LO + (uint32_t)(wr + lrow) * 528;

    for (int g = 0; g < 8; ++g) {
        if (g == 4) {
            #pragma unroll
            for (int t = 0; t < 16; ++t) {
                int c = nh * 128 + t * 8 + qc;
                __nv_bfloat162 hi2, lo2;
                split2(lrelu(acc1[t][0]), lrelu(acc1[t][1]), hi2, lo2);
                uint32_t o0 = (uint32_t)(wr + qr) * 528 + c * 2;
                *(__nv_bfloat162*)(sm + SA_HI + o0) = hi2;
                *(__nv_bfloat162*)(sm + SA_LO + o0) = lo2;
                split2(lrelu(acc1[t][2]), lrelu(acc1[t][3]), hi2, lo2);
                uint32_t o1 = (uint32_t)(wr + qr + 8) * 528 + c * 2;
                *(__nv_bfloat162*)(sm + SA_HI + o1) = hi2;
                *(__nv_bfloat162*)(sm + SA_LO + o1) = lo2;
            }
            #pragma unroll
            for (int t = 0; t < 8; ++t) {
                int c = nh * 64 + t * 8 + qc;
                acc2[t][0] = sB2[c]; acc2[t][1] = sB2[c + 1];
                acc2[t][2] = sB2[c]; acc2[t][3] = sB2[c + 1];
            }
        }

        if (g + 1 < 8) { CP_WAIT(1); } else { CP_WAIT(0); }
        __syncthreads();

        const uint32_t slot = wbase + (uint32_t)(g & 1) * 67584u;
        const int kb = (g < 4 ? g : g - 4) * 64;

        #pragma unroll
        for (int j = 0; j < 4; ++j) {
            const int k0 = kb + j * 16;
            unsigned ahi[4], alo[4];
            ldsm4(ahi, aHi + (uint32_t)(k0 + lcol8) * 2);
            ldsm4(alo, aLo + (uint32_t)(k0 + lcol8) * 2);
            if (g < 4) {
                compute_k256(acc1, ahi, alo, slot + (uint32_t)(j * 16 + lrow) * 528, 33792u, nh, lcol8);
            } else {
                compute_k128(acc2, ahi, alo, slot + (uint32_t)(j * 16 + lrow) * 272, 17408u, nh, lcol8);
            }
        }
        __syncthreads();
        if (g + 2 < 8) load_slab64(g + 2, wbase, tid);
    }

    #pragma unroll
    for (int t = 0; t < 8; ++t) {
        int c = nh * 64 + t * 8 + qc;
        int r = row0 + wr + qr;
        if (r < n)
            *reinterpret_cast<float2*>(Y + (size_t)r * 128 + c) =
                make_float2(lrelu(acc2[t][0]), lrelu(acc2[t][1]));
        if (r + 8 < n)
            *reinterpret_cast<float2*>(Y + (size_t)(r + 8) * 128 + c) =
                make_float2(lrelu(acc2[t][2]), lrelu(acc2[t][3]));
    }
}

// tail: levels 6..0 in one CTA, 56 stages, K-slab 64.
__global__ void __launch_bounds__(256, 1)
tail_kernel(float* __restrict__ out,
            const float* __restrict__ b1, const float* __restrict__ b2)
{
    extern __shared__ __align__(16) char sm[];
    const uint32_t base = smem_u32(sm);
    const int tid = threadIdx.x, wid = tid >> 5, lane = tid & 31;
    const int wr = (wid & 3) * 16, nh = wid >> 2;
    const int lrow = lane & 15, lcol8 = (lane >> 4) * 8;
    const int qr = lane >> 2, qc = (lane & 3) * 2;
    const uint32_t wbase = base + S_W;

    load_slab64(0, wbase, tid);
    load_slab64(1, wbase, tid);

    ((float*)(sm + S_SB1))[tid] = b1[tid];
    if (tid < 128) ((float*)(sm + S_SB2))[tid] = b2[tid];

    {
        const float* X = out + 127 * 128;
        for (int idx = tid; idx < 64 * 64; idx += 256) {
            int r = idx >> 6, c4 = idx & 63;
            float4 v = reinterpret_cast<const float4*>(X)[r * 64 + c4];
            __nv_bfloat162 h0, l0, h1, l1;
            split2(v.x, v.y, h0, l0); split2(v.z, v.w, h1, l1);
            uint32_t off = (uint32_t)r * 528 + c4 * 8;
            *(__nv_bfloat162*)(sm + SA_HI + off)     = h0;
            *(__nv_bfloat162*)(sm + SA_HI + off + 4) = h1;
            *(__nv_bfloat162*)(sm + SA_LO + off)     = l0;
            *(__nv_bfloat162*)(sm + SA_LO + off + 4) = l1;
        }
    }
    __syncthreads();

    const float* sB1 = (const float*)(sm + S_SB1);
    const float* sB2 = (const float*)(sm + S_SB2);

    float acc1[16][4], acc2[8][4];
    #pragma unroll
    for (int t = 0; t < 16; ++t) {
        int c = nh * 128 + t * 8 + qc;
        acc1[t][0] = sB1[c]; acc1[t][1] = sB1[c + 1];
        acc1[t][2] = sB1[c]; acc1[t][3] = sB1[c + 1];
    }

    const uint32_t aHi = base + SA_HI + (uint32_t)(wr + lrow) * 528;
    const uint32_t aLo = base + SA_LO + (uint32_t)(wr + lrow) * 528;

    int n = 64;
    constexpr int GT = 7 * 8;
    for (int g = 0; g < GT; ++g) {
        const int ph = g & 7;
        if (ph == 0 && g > 0) {
            const int lvDone = 7 - (g >> 3);
            float* Y = out + (((size_t)1 << lvDone) - 1) * 128;
            #pragma unroll
            for (int t = 0; t < 8; ++t) {
                int c = nh * 64 + t * 8 + qc;
                #pragma unroll
                for (int h = 0; h < 2; ++h) {
                    int r = wr + qr + h * 8;
                    float v0 = lrelu(acc2[t][2 * h]);
                    float v1 = lrelu(acc2[t][2 * h + 1]);
                    if (r < n)
                        *reinterpret_cast<float2*>(Y + (size_t)r * 128 + c) = make_float2(v0, v1);
                    __nv_bfloat162 hi2, lo2;
                    split2(v0, v1, hi2, lo2);
                    uint32_t off = (uint32_t)(r >> 1) * 528 + ((r & 1) * 128 + c) * 2;
                    *(__nv_bfloat162*)(sm + SA_HI + off) = hi2;
                    *(__nv_bfloat162*)(sm + SA_LO + off) = lo2;
                }
            }
            #pragma unroll
            for (int t = 0; t < 16; ++t) {
                int c = nh * 128 + t * 8 + qc;
                acc1[t][0] = sB1[c]; acc1[t][1] = sB1[c + 1];
                acc1[t][2] = sB1[c]; acc1[t][3] = sB1[c + 1];
            }
            n >>= 1;
        }
        if (ph == 4) {
            #pragma unroll
            for (int t = 0; t < 16; ++t) {
                int c = nh * 128 + t * 8 + qc;
                __nv_bfloat162 hi2, lo2;
                split2(lrelu(acc1[t][0]), lrelu(acc1[t][1]), hi2, lo2);
                uint32_t o0 = (uint32_t)(wr + qr) * 528 + c * 2;
                *(__nv_bfloat162*)(sm + SA_HI + o0) = hi2;
                *(__nv_bfloat162*)(sm + SA_LO + o0) = lo2;
                split2(lrelu(acc1[t][2]), lrelu(acc1[t][3]), hi2, lo2);
                uint32_t o1 = (uint32_t)(wr + qr + 8) * 528 + c * 2;
                *(__nv_bfloat162*)(sm + SA_HI + o1) = hi2;
                *(__nv_bfloat162*)(sm + SA_LO + o1) = lo2;
            }
            #pragma unroll
            for (int t = 0; t < 8; ++t) {
                int c = nh * 64 + t * 8 + qc;
                acc2[t][0] = sB2[c]; acc2[t][1] = sB2[c + 1];
                acc2[t][2] = sB2[c]; acc2[t][3] = sB2[c + 1];
            }
        }

        if (g + 1 < GT) { CP_WAIT(1); } else { CP_WAIT(0); }
        __syncthreads();

        const uint32_t slot = wbase + (uint32_t)(g & 1) * 67584u;
        const int kb = (ph < 4 ? ph : ph - 4) * 64;

        #pragma unroll
        for (int j = 0; j < 4; ++j) {
            const int k0 = kb + j * 16;
            unsigned ahi[4], alo[4];
            ldsm4(ahi, aHi + (uint32_t)(k0 + lcol8) * 2);
            ldsm4(alo, aLo + (uint32_t)(k0 + lcol8) * 2);
            if (ph < 4) {
                compute_k256(acc1, ahi, alo, slot + (uint32_t)(j * 16 + lrow) * 528, 33792u, nh, lcol8);
            } else {
                compute_k128(acc2, ahi, alo, slot + (uint32_t)(j * 16 + lrow) * 272, 17408u, nh, lcol8);
            }
        }
        __syncthreads();
        if (g + 2 < GT) load_slab64((g + 2) & 7, wbase, tid);
    }

    // level 0 (root)
    #pragma unroll
    for (int t = 0; t < 8; ++t) {
        int c = nh * 64 + t * 8 + qc;
        #pragma unroll
        for (int h = 0; h < 2; ++h) {
            int r = wr + qr + h * 8;
            if (r < 1)
                *reinterpret_cast<float2*>(out + (size_t)r * 128 + c) =
                    make_float2(lrelu(acc2[t][2 * h]), lrelu(acc2[t][2 * h + 1]));
        }
    }
}

extern "C" void kernel_launch(void* const* d_in, const int* in_sizes, int n_in,
                              void* d_out, int out_size)
{
    const float* leaf = (const float*)d_in[0];
    const float* We   = (const float*)d_in[1];
    const float* be   = (const float*)d_in[2];
    const float* W1   = (const float*)d_in[3];
    const float* b1   = (const float*)d_in[4];
    const float* W2   = (const float*)d_in[5];
    const float* b2   = (const float*)d_in[6];
    float* out = (float*)d_out;

    cudaFuncSetAttribute(level_kernel<true>,  cudaFuncAttributeMaxDynamicSharedMemorySize, SMEM_LVL);
    cudaFuncSetAttribute(level_kernel<false>, cudaFuncAttributeMaxDynamicSharedMemorySize, SMEM_LVL);
    cudaFuncSetAttribute(small_kernel, cudaFuncAttributeMaxDynamicSharedMemorySize, SMEM_SMALL);
    cudaFuncSetAttribute(tail_kernel,  cudaFuncAttributeMaxDynamicSharedMemorySize, SMEM_SMALL);

    prep_kernel<<<256, 256>>>(W1, W2, We);

    const size_t leaf_start = (size_t)(1u << DEPTH) - 1;
    float* Yemb = out + leaf_start * 128;

    for (int l = DEPTH - 1; l >= 7; --l) {
        const int n = 1 << l;
        const size_t p0 = (size_t)(1u << l) - 1;
        float* Y = out + p0 * 128;
        const int grid = (n + 63) / 64;
        if (l == DEPTH - 1) {
            level_kernel<true><<<grid, 256, SMEM_LVL>>>(leaf, Y, Yemb, b1, b2, be, n);
        } else if (l >= 14) {
            const float* X = out + (2 * p0 + 1) * 128;
            level_kernel<false><<<grid, 256, SMEM_LVL>>>(X, Y, Yemb, b1, b2, be, n);
        } else {
            const float* X = out + (2 * p0 + 1) * 128;
            small_kernel<<<grid, 256, SMEM_SMALL>>>(X, Y, b1, b2, n);
        }
    }
    tail_kernel<<<1, 256, SMEM_SMALL>>>(out, b1, b2);
}

// round 16
// speedup vs baseline: 1.0131x; 1.0012x over previous
#include <cuda_runtime.h>
#include <cuda_bf16.h>
#include <cstdint>

// R16: R15 with the W2 super-slab gmem offset fixed (s*8192, was s*16384 —
// a 32-k-row W2 slab is 32*128*2 = 8192 bytes). Merged layer-2 stages:
// 32 k-rows/stage, G 32->24 big / 36->28 LEAF. Accumulation order unchanged
// -> rel_err must be exactly 5.018873e-06.

static __forceinline__ __device__ float lrelu(float v) { return v > 0.0f ? v : 0.01f * v; }

constexpr int DEPTH = 18;
// big-level kernel smem map
constexpr int SA_HI = 0;        // [64][528B] bf16
constexpr int SA_LO = 33792;
constexpr int W_ST  = 67584;    // 2 slots x 17408
constexpr int SB1   = 102400;
constexpr int SB2   = 103424;
constexpr int SBE   = 103936;
constexpr int SMEM_LVL = 104448;

// slab64 kernels smem map
constexpr int S_W   = 67584;              // 2 slots x 67584
constexpr int S_SB1 = 202752;
constexpr int S_SB2 = 203776;
constexpr int SMEM_SMALL = 204288;

// prepped split weights (row-major bf16)
__device__ __align__(16) __nv_bfloat16 W1hi_d[65536];   // [256][256]
__device__ __align__(16) __nv_bfloat16 W1lo_d[65536];
__device__ __align__(16) __nv_bfloat16 W2hi_d[32768];   // [256][128]
__device__ __align__(16) __nv_bfloat16 W2lo_d[32768];
__device__ __align__(16) __nv_bfloat16 WBhi_d[16384];   // blockdiag(We,We) [64][256]
__device__ __align__(16) __nv_bfloat16 WBlo_d[16384];

static __forceinline__ __device__ uint32_t smem_u32(const void* p) {
    uint32_t a;
    asm("{ .reg .u64 t; cvta.to.shared.u64 t, %1; cvt.u32.u64 %0, t; }" : "=r"(a) : "l"(p));
    return a;
}
static __forceinline__ __device__ void cp16(uint32_t d, const void* s) {
    asm volatile("cp.async.cg.shared.global [%0], [%1], 16;" :: "r"(d), "l"(s));
}
#define CP_COMMIT() asm volatile("cp.async.commit_group;" ::: "memory")
#define CP_WAIT(N)  asm volatile("cp.async.wait_group %0;" :: "n"(N) : "memory")

static __forceinline__ __device__ void ldsm4(unsigned* r, uint32_t a) {
    asm volatile("ldmatrix.sync.aligned.m8n8.x4.shared.b16 {%0,%1,%2,%3}, [%4];"
                 : "=r"(r[0]), "=r"(r[1]), "=r"(r[2]), "=r"(r[3]) : "r"(a));
}
static __forceinline__ __device__ void ldsm4t(unsigned* r, uint32_t a) {
    asm volatile("ldmatrix.sync.aligned.m8n8.x4.trans.shared.b16 {%0,%1,%2,%3}, [%4];"
                 : "=r"(r[0]), "=r"(r[1]), "=r"(r[2]), "=r"(r[3]) : "r"(a));
}
static __forceinline__ __device__ void mma_bf16(float* c, const unsigned* a, const unsigned* b) {
    asm volatile("mma.sync.aligned.m16n8k16.row.col.f32.bf16.bf16.f32 "
                 "{%0,%1,%2,%3}, {%4,%5,%6,%7}, {%8,%9}, {%0,%1,%2,%3};"
                 : "+f"(c[0]), "+f"(c[1]), "+f"(c[2]), "+f"(c[3])
                 : "r"(a[0]), "r"(a[1]), "r"(a[2]), "r"(a[3]), "r"(b[0]), "r"(b[1]));
}
static __forceinline__ __device__ void split2(float h0, float h1,
                                              __nv_bfloat162& hi, __nv_bfloat162& lo) {
    hi = __floats2bfloat162_rn(h0, h1);
    lo = __floats2bfloat162_rn(h0 - __bfloat162float(hi.x), h1 - __bfloat162float(hi.y));
}

__global__ void prep_kernel(const float* __restrict__ W1, const float* __restrict__ W2,
                            const float* __restrict__ We) {
    int t = blockIdx.x * 256 + threadIdx.x;
    if (t < 65536) {
        float f = W1[t];
        __nv_bfloat16 hi = __float2bfloat16(f);
        W1hi_d[t] = hi; W1lo_d[t] = __float2bfloat16(f - __bfloat162float(hi));
    }
    if (t < 32768) {
        float f = W2[t];
        __nv_bfloat16 hi = __float2bfloat16(f);
        W2hi_d[t] = hi; W2lo_d[t] = __float2bfloat16(f - __bfloat162float(hi));
    }
    if (t < 16384) {
        int k = t >> 8, c = t & 255;
        float f = 0.0f;
        if (k < 32 && c < 128)   f = We[k * 128 + c];
        if (k >= 32 && c >= 128) f = We[(k - 32) * 128 + (c - 128)];
        __nv_bfloat16 hi = __float2bfloat16(f);
        WBhi_d[t] = hi; WBlo_d[t] = __float2bfloat16(f - __bfloat162float(hi));
    }
}

// ---------- big-level slab loader ----------
// K256-type slabs (WB/W1, 16 k-rows): [hi 16x528 | lo 16x528] = 16896 B.
// W2 super-slabs (32 k-rows): two 16-row sub-slabs [hi 16x272 | lo 16x272]
// (8704 B each) at slot offsets 0 and 8704. One commit per stage.
template<bool LEAF>
static __forceinline__ __device__ void load_slab(int g, uint32_t base, int tid) {
    uint32_t slot = base + W_ST + (uint32_t)(g & 1) * 17408u;
    constexpr int W2_AT = LEAF ? 20 : 16;
    if (g < W2_AT) {
        const char *hi, *lo;
        if (LEAF && g < 4) {
            hi = (const char*)WBhi_d + (size_t)g * 8192;
            lo = (const char*)WBlo_d + (size_t)g * 8192;
        } else {
            int s = LEAF ? (g - 4) : g;
            hi = (const char*)W1hi_d + (size_t)s * 8192;
            lo = (const char*)W1lo_d + (size_t)s * 8192;
        }
        #pragma unroll
        for (int j = 0; j < 4; ++j) {
            int idx = tid + j * 256;
            int part = idx >> 9, rc = idx & 511, r = rc >> 5, c = rc & 31;
            cp16(slot + part * 8448 + r * 528 + c * 16, (part ? lo : hi) + r * 512 + c * 16);
        }
    } else {
        int s = g - W2_AT;                          // 0..7, k rows s*32..+31
        const char* hi = (const char*)W2hi_d + (size_t)s * 8192;   // FIXED: 32 rows * 256 B
        const char* lo = (const char*)W2lo_d + (size_t)s * 8192;
        #pragma unroll
        for (int j = 0; j < 4; ++j) {
            int idx = tid + j * 256;                // 1024 chunks
            int sub = idx >> 9, rc = idx & 511;
            int part = rc >> 8, rr = (rc >> 4) & 15, c = rc & 15;
            cp16(slot + sub * 8704 + part * 4352 + rr * 272 + c * 16,
                 (part ? lo : hi) + sub * 4096 + rr * 256 + c * 16);   // FIXED: sub-slab = 16 rows = 4096 B
        }
    }
    CP_COMMIT();
}

// ---------- slab64 loader: g 0..3 -> W1 64-row slabs, 4..7 -> W2 ----------
static __forceinline__ __device__ void load_slab64(int g, uint32_t wbase, int tid) {
    uint32_t slot = wbase + (uint32_t)(g & 1) * 67584u;
    if (g < 4) {
        const char* hi = (const char*)W1hi_d + (size_t)g * 32768;
        const char* lo = (const char*)W1lo_d + (size_t)g * 32768;
        #pragma unroll
        for (int j = 0; j < 16; ++j) {
            int idx = tid + j * 256;
            int part = idx >> 11, rc = idx & 2047, r = rc >> 5, c = rc & 31;
            cp16(slot + part * 33792 + r * 528 + c * 16, (part ? lo : hi) + r * 512 + c * 16);
        }
    } else {
        const char* hi = (const char*)W2hi_d + (size_t)(g - 4) * 16384;
        const char* lo = (const char*)W2lo_d + (size_t)(g - 4) * 16384;
        #pragma unroll
        for (int j = 0; j < 8; ++j) {
            int idx = tid + j * 256;
            int part = idx >> 10, rc = idx & 1023, r = rc >> 4, c = rc & 15;
            cp16(slot + part * 17408 + r * 272 + c * 16, (part ? lo : hi) + r * 256 + c * 16);
        }
    }
    CP_COMMIT();
}

// ---------- compute sub-stages (16x128 warp tile) ----------
static __forceinline__ __device__ void compute_k256(
    float acc1[16][4], const unsigned ahi[4], const unsigned alo[4],
    uint32_t brow, uint32_t lo_off, int nh, int lcol8)
{
    #pragma unroll
    for (int p = 0; p < 8; ++p) {
        int nb = nh * 128 + p * 16;
        unsigned bh[4], bl[4];
        ldsm4t(bh, brow + (uint32_t)(nb + lcol8) * 2);
        ldsm4t(bl, brow + lo_off + (uint32_t)(nb + lcol8) * 2);
        mma_bf16(acc1[2 * p],     ahi, bh);
        mma_bf16(acc1[2 * p + 1], ahi, bh + 2);
        mma_bf16(acc1[2 * p],     alo, bh);
        mma_bf16(acc1[2 * p + 1], alo, bh + 2);
        mma_bf16(acc1[2 * p],     ahi, bl);
        mma_bf16(acc1[2 * p + 1], ahi, bl + 2);
    }
}
static __forceinline__ __device__ void compute_k128(
    float acc2[8][4], const unsigned ahi[4], const unsigned alo[4],
    uint32_t brow, uint32_t lo_off, int nh, int lcol8)
{
    #pragma unroll
    for (int p = 0; p < 4; ++p) {
        int nb = nh * 64 + p * 16;
        unsigned bh[4], bl[4];
        ldsm4t(bh, brow + (uint32_t)(nb + lcol8) * 2);
        ldsm4t(bl, brow + lo_off + (uint32_t)(nb + lcol8) * 2);
        mma_bf16(acc2[2 * p],     ahi, bh);
        mma_bf16(acc2[2 * p + 1], ahi, bh + 2);
        mma_bf16(acc2[2 * p],     alo, bh);
        mma_bf16(acc2[2 * p + 1], alo, bh + 2);
        mma_bf16(acc2[2 * p],     ahi, bl);
        mma_bf16(acc2[2 * p + 1], ahi, bl + 2);
    }
}

// ---------- big-level kernel (levels 17..14) ----------
template<bool LEAF>
__global__ void __launch_bounds__(256, 2)
level_kernel(const float* __restrict__ X, float* __restrict__ Y,
             float* __restrict__ Yemb,
             const float* __restrict__ b1, const float* __restrict__ b2,
             const float* __restrict__ be, int n)
{
    extern __shared__ __align__(16) char sm[];
    const uint32_t base = smem_u32(sm);
    const int tid = threadIdx.x, wid = tid >> 5, lane = tid & 31;
    const int wr = (wid & 3) * 16;
    const int nh = wid >> 2;
    const int row0 = blockIdx.x * 64;
    const int lrow = lane & 15, lcol8 = (lane >> 4) * 8;
    const int qr = lane >> 2, qc = (lane & 3) * 2;

    constexpr int G = LEAF ? 28 : 24;            // emb(4) + l1(16) + l2(8 merged)
    constexpr int EPI1_AT = LEAF ? 20 : 16;

    load_slab<LEAF>(0, base, tid);
    load_slab<LEAF>(1, base, tid);

    ((float*)(sm + SB1))[tid] = b1[tid];
    if (tid < 128) ((float*)(sm + SB2))[tid] = b2[tid];
    if (tid < 128) ((float*)(sm + SBE))[tid] = be[tid];

    if (LEAF) {
        const float* Xb = X + (size_t)row0 * 64;
        for (int idx = tid; idx < 64 * 16; idx += 256) {
            int r = idx >> 4, c4 = idx & 15;
            float4 v = make_float4(0.f, 0.f, 0.f, 0.f);
            if (row0 + r < n) v = reinterpret_cast<const float4*>(Xb)[r * 16 + c4];
            __nv_bfloat162 h0, l0, h1, l1;
            split2(v.x, v.y, h0, l0); split2(v.z, v.w, h1, l1);
            uint32_t off = (uint32_t)r * 528 + c4 * 8;
            *(__nv_bfloat162*)(sm + SA_HI + off)     = h0;
            *(__nv_bfloat162*)(sm + SA_HI + off + 4) = h1;
            *(__nv_bfloat162*)(sm + SA_LO + off)     = l0;
            *(__nv_bfloat162*)(sm + SA_LO + off + 4) = l1;
        }
    } else {
        for (int idx = tid; idx < 64 * 64; idx += 256) {
            int r = idx >> 6, c4 = idx & 63;
            float4 v = make_float4(0.f, 0.f, 0.f, 0.f);
            if (row0 + r < n) v = reinterpret_cast<const float4*>(X)[(size_t)(row0 + r) * 64 + c4];
            __nv_bfloat162 h0, l0, h1, l1;
            split2(v.x, v.y, h0, l0); split2(v.z, v.w, h1, l1);
            uint32_t off = (uint32_t)r * 528 + c4 * 8;
            *(__nv_bfloat162*)(sm + SA_HI + off)     = h0;
            *(__nv_bfloat162*)(sm + SA_HI + off + 4) = h1;
            *(__nv_bfloat162*)(sm + SA_LO + off)     = l0;
            *(__nv_bfloat162*)(sm + SA_LO + off + 4) = l1;
        }
    }
    __syncthreads();

    const float* sB1 = (const float*)(sm + SB1);
    const float* sB2 = (const float*)(sm + SB2);
    const float* sBE = (const float*)(sm + SBE);

    float acc1[16][4];   // emb(leaf)/layer1: warp 16 x 128 (cols nh*128..)
    float acc2[8][4];    // layer2: warp 16 x 64 (cols nh*64..)
    #pragma unroll
    for (int t = 0; t < 16; ++t) {
        int c = nh * 128 + t * 8 + qc;
        float v0 = LEAF ? sBE[c & 127] : sB1[c];
        float v1 = LEAF ? sBE[(c + 1) & 127] : sB1[c + 1];
        acc1[t][0] = v0; acc1[t][1] = v1; acc1[t][2] = v0; acc1[t][3] = v1;
    }

    const uint32_t aHi = base + SA_HI + (uint32_t)(wr + lrow) * 528;
    const uint32_t aLo = base + SA_LO + (uint32_t)(wr + lrow) * 528;

    for (int g = 0; g < G; ++g) {
        if (LEAF && g == 4) {
            #pragma unroll
            for (int t = 0; t < 16; ++t) {
                int c = nh * 128 + t * 8 + qc;
                float v0 = lrelu(acc1[t][0]), v1 = lrelu(acc1[t][1]);
                float v2 = lrelu(acc1[t][2]), v3 = lrelu(acc1[t][3]);
                __nv_bfloat162 hi2, lo2;
                split2(v0, v1, hi2, lo2);
                uint32_t o0 = (uint32_t)(wr + qr) * 528 + c * 2;
                *(__nv_bfloat162*)(sm + SA_HI + o0) = hi2;
                *(__nv_bfloat162*)(sm + SA_LO + o0) = lo2;
                if (row0 + wr + qr < n)
                    *reinterpret_cast<float2*>(Yemb + (size_t)(row0 + wr + qr) * 256 + c) = make_float2(v0, v1);
                split2(v2, v3, hi2, lo2);
                uint32_t o1 = (uint32_t)(wr + qr + 8) * 528 + c * 2;
                *(__nv_bfloat162*)(sm + SA_HI + o1) = hi2;
                *(__nv_bfloat162*)(sm + SA_LO + o1) = lo2;
                if (row0 + wr + qr + 8 < n)
                    *reinterpret_cast<float2*>(Yemb + (size_t)(row0 + wr + qr + 8) * 256 + c) = make_float2(v2, v3);
            }
            #pragma unroll
            for (int t = 0; t < 16; ++t) {
                int c = nh * 128 + t * 8 + qc;
                acc1[t][0] = sB1[c]; acc1[t][1] = sB1[c + 1];
                acc1[t][2] = sB1[c]; acc1[t][3] = sB1[c + 1];
            }
        }
        if (g == EPI1_AT) {
            #pragma unroll
            for (int t = 0; t < 16; ++t) {
                int c = nh * 128 + t * 8 + qc;
                __nv_bfloat162 hi2, lo2;
                split2(lrelu(acc1[t][0]), lrelu(acc1[t][1]), hi2, lo2);
                uint32_t o0 = (uint32_t)(wr + qr) * 528 + c * 2;
                *(__nv_bfloat162*)(sm + SA_HI + o0) = hi2;
                *(__nv_bfloat162*)(sm + SA_LO + o0) = lo2;
                split2(lrelu(acc1[t][2]), lrelu(acc1[t][3]), hi2, lo2);
                uint32_t o1 = (uint32_t)(wr + qr + 8) * 528 + c * 2;
                *(__nv_bfloat162*)(sm + SA_HI + o1) = hi2;
                *(__nv_bfloat162*)(sm + SA_LO + o1) = lo2;
            }
            #pragma unroll
            for (int t = 0; t < 8; ++t) {
                int c = nh * 64 + t * 8 + qc;
                acc2[t][0] = sB2[c]; acc2[t][1] = sB2[c + 1];
                acc2[t][2] = sB2[c]; acc2[t][3] = sB2[c + 1];
            }
        }

        if (g + 1 < G) { CP_WAIT(1); } else { CP_WAIT(0); }
        __syncthreads();

        const uint32_t slot = base + W_ST + (uint32_t)(g & 1) * 17408u;

        if (g < EPI1_AT) {
            int k0;
            if (LEAF) k0 = (g < 4) ? g * 16 : (g - 4) * 16;
            else      k0 = g * 16;
            unsigned ahi[4], alo[4];
            ldsm4(ahi, aHi + (uint32_t)(k0 + lcol8) * 2);
            ldsm4(alo, aLo + (uint32_t)(k0 + lcol8) * 2);
            compute_k256(acc1, ahi, alo, slot + (uint32_t)lrow * 528, 8448u, nh, lcol8);
        } else {
            const int s = g - EPI1_AT;              // 0..7
            #pragma unroll
            for (int j = 0; j < 2; ++j) {
                const int k0 = s * 32 + j * 16;
                unsigned ahi[4], alo[4];
                ldsm4(ahi, aHi + (uint32_t)(k0 + lcol8) * 2);
                ldsm4(alo, aLo + (uint32_t)(k0 + lcol8) * 2);
                compute_k128(acc2, ahi, alo,
                             slot + (uint32_t)j * 8704 + (uint32_t)lrow * 272, 4352u, nh, lcol8);
            }
        }
        __syncthreads();
        if (g + 2 < G) load_slab<LEAF>(g + 2, base, tid);
    }

    #pragma unroll
    for (int t = 0; t < 8; ++t) {
        int c = nh * 64 + t * 8 + qc;
        int r = row0 + wr + qr;
        if (r < n)
            *reinterpret_cast<float2*>(Y + (size_t)r * 128 + c) =
                make_float2(lrelu(acc2[t][0]), lrelu(acc2[t][1]));
        if (r + 8 < n)
            *reinterpret_cast<float2*>(Y + (size_t)(r + 8) * 128 + c) =
                make_float2(lrelu(acc2[t][2]), lrelu(acc2[t][3]));
    }
}

// small levels 13..7: one level per launch, 8 stages, K-slab 64.
__global__ void __launch_bounds__(256, 1)
small_kernel(const float* __restrict__ X, float* __restrict__ Y,
             const float* __restrict__ b1, const float* __restrict__ b2, int n)
{
    extern __shared__ __align__(16) char sm[];
    const uint32_t base = smem_u32(sm);
    const int tid = threadIdx.x, wid = tid >> 5, lane = tid & 31;
    const int wr = (wid & 3) * 16, nh = wid >> 2;
    const int row0 = blockIdx.x * 64;
    const int lrow = lane & 15, lcol8 = (lane >> 4) * 8;
    const int qr = lane >> 2, qc = (lane & 3) * 2;
    const uint32_t wbase = base + S_W;

    load_slab64(0, wbase, tid);
    load_slab64(1, wbase, tid);

    ((float*)(sm + S_SB1))[tid] = b1[tid];
    if (tid < 128) ((float*)(sm + S_SB2))[tid] = b2[tid];

    for (int idx = tid; idx < 64 * 64; idx += 256) {
        int r = idx >> 6, c4 = idx & 63;
        float4 v = make_float4(0.f, 0.f, 0.f, 0.f);
        if (row0 + r < n) v = reinterpret_cast<const float4*>(X)[(size_t)(row0 + r) * 64 + c4];
        __nv_bfloat162 h0, l0, h1, l1;
        split2(v.x, v.y, h0, l0); split2(v.z, v.w, h1, l1);
        uint32_t off = (uint32_t)r * 528 + c4 * 8;
        *(__nv_bfloat162*)(sm + SA_HI + off)     = h0;
        *(__nv_bfloat162*)(sm + SA_HI + off + 4) = h1;
        *(__nv_bfloat162*)(sm + SA_LO + off)     = l0;
        *(__nv_bfloat162*)(sm + SA_LO + off + 4) = l1;
    }
    __syncthreads();

    const float* sB1 = (const float*)(sm + S_SB1);
    const float* sB2 = (const float*)(sm + S_SB2);

    float acc1[16][4], acc2[8][4];
    #pragma unroll
    for (int t = 0; t < 16; ++t) {
        int c = nh * 128 + t * 8 + qc;
        acc1[t][0] = sB1[c]; acc1[t][1] = sB1[c + 1];
        acc1[t][2] = sB1[c]; acc1[t][3] = sB1[c + 1];
    }

    const uint32_t aHi = base + SA_HI + (uint32_t)(wr + lrow) * 528;
    const uint32_t aLo = base + SA_LO + (uint32_t)(wr + lrow) * 528;

    for (int g = 0; g < 8; ++g) {
        if (g == 4) {
            #pragma unroll
            for (int t = 0; t < 16; ++t) {
                int c = nh * 128 + t * 8 + qc;
                __nv_bfloat162 hi2, lo2;
                split2(lrelu(acc1[t][0]), lrelu(acc1[t][1]), hi2, lo2);
                uint32_t o0 = (uint32_t)(wr + qr) * 528 + c * 2;
                *(__nv_bfloat162*)(sm + SA_HI + o0) = hi2;
                *(__nv_bfloat162*)(sm + SA_LO + o0) = lo2;
                split2(lrelu(acc1[t][2]), lrelu(acc1[t][3]), hi2, lo2);
                uint32_t o1 = (uint32_t)(wr + qr + 8) * 528 + c * 2;
                *(__nv_bfloat162*)(sm + SA_HI + o1) = hi2;
                *(__nv_bfloat162*)(sm + SA_LO + o1) = lo2;
            }
            #pragma unroll
            for (int t = 0; t < 8; ++t) {
                int c = nh * 64 + t * 8 + qc;
                acc2[t][0] = sB2[c]; acc2[t][1] = sB2[c + 1];
                acc2[t][2] = sB2[c]; acc2[t][3] = sB2[c + 1];
            }
        }

        if (g + 1 < 8) { CP_WAIT(1); } else { CP_WAIT(0); }
        __syncthreads();

        const uint32_t slot = wbase + (uint32_t)(g & 1) * 67584u;
        const int kb = (g < 4 ? g : g - 4) * 64;

        #pragma unroll
        for (int j = 0; j < 4; ++j) {
            const int k0 = kb + j * 16;
            unsigned ahi[4], alo[4];
            ldsm4(ahi, aHi + (uint32_t)(k0 + lcol8) * 2);
            ldsm4(alo, aLo + (uint32_t)(k0 + lcol8) * 2);
            if (g < 4) {
                compute_k256(acc1, ahi, alo, slot + (uint32_t)(j * 16 + lrow) * 528, 33792u, nh, lcol8);
            } else {
                compute_k128(acc2, ahi, alo, slot + (uint32_t)(j * 16 + lrow) * 272, 17408u, nh, lcol8);
            }
        }
        __syncthreads();
        if (g + 2 < 8) load_slab64(g + 2, wbase, tid);
    }

    #pragma unroll
    for (int t = 0; t < 8; ++t) {
        int c = nh * 64 + t * 8 + qc;
        int r = row0 + wr + qr;
        if (r < n)
            *reinterpret_cast<float2*>(Y + (size_t)r * 128 + c) =
                make_float2(lrelu(acc2[t][0]), lrelu(acc2[t][1]));
        if (r + 8 < n)
            *reinterpret_cast<float2*>(Y + (size_t)(r + 8) * 128 + c) =
                make_float2(lrelu(acc2[t][2]), lrelu(acc2[t][3]));
    }
}

// tail: levels 6..0 in one CTA, 56 stages, K-slab 64.
__global__ void __launch_bounds__(256, 1)
tail_kernel(float* __restrict__ out,
            const float* __restrict__ b1, const float* __restrict__ b2)
{
    extern __shared__ __align__(16) char sm[];
    const uint32_t base = smem_u32(sm);
    const int tid = threadIdx.x, wid = tid >> 5, lane = tid & 31;
    const int wr = (wid & 3) * 16, nh = wid >> 2;
    const int lrow = lane & 15, lcol8 = (lane >> 4) * 8;
    const int qr = lane >> 2, qc = (lane & 3) * 2;
    const uint32_t wbase = base + S_W;

    load_slab64(0, wbase, tid);
    load_slab64(1, wbase, tid);

    ((float*)(sm + S_SB1))[tid] = b1[tid];
    if (tid < 128) ((float*)(sm + S_SB2))[tid] = b2[tid];

    {
        const float* X = out + 127 * 128;
        for (int idx = tid; idx < 64 * 64; idx += 256) {
            int r = idx >> 6, c4 = idx & 63;
            float4 v = reinterpret_cast<const float4*>(X)[r * 64 + c4];
            __nv_bfloat162 h0, l0, h1, l1;
            split2(v.x, v.y, h0, l0); split2(v.z, v.w, h1, l1);
            uint32_t off = (uint32_t)r * 528 + c4 * 8;
            *(__nv_bfloat162*)(sm + SA_HI + off)     = h0;
            *(__nv_bfloat162*)(sm + SA_HI + off + 4) = h1;
            *(__nv_bfloat162*)(sm + SA_LO + off)     = l0;
            *(__nv_bfloat162*)(sm + SA_LO + off + 4) = l1;
        }
    }
    __syncthreads();

    const float* sB1 = (const float*)(sm + S_SB1);
    const float* sB2 = (const float*)(sm + S_SB2);

    float acc1[16][4], acc2[8][4];
    #pragma unroll
    for (int t = 0; t < 16; ++t) {
        int c = nh * 128 + t * 8 + qc;
        acc1[t][0] = sB1[c]; acc1[t][1] = sB1[c + 1];
        acc1[t][2] = sB1[c]; acc1[t][3] = sB1[c + 1];
    }

    const uint32_t aHi = base + SA_HI + (uint32_t)(wr + lrow) * 528;
    const uint32_t aLo = base + SA_LO + (uint32_t)(wr + lrow) * 528;

    int n = 64;
    constexpr int GT = 7 * 8;
    for (int g = 0; g < GT; ++g) {
        const int ph = g & 7;
        if (ph == 0 && g > 0) {
            const int lvDone = 7 - (g >> 3);
            float* Y = out + (((size_t)1 << lvDone) - 1) * 128;
            #pragma unroll
            for (int t = 0; t < 8; ++t) {
                int c = nh * 64 + t * 8 + qc;
                #pragma unroll
                for (int h = 0; h < 2; ++h) {
                    int r = wr + qr + h * 8;
                    float v0 = lrelu(acc2[t][2 * h]);
                    float v1 = lrelu(acc2[t][2 * h + 1]);
                    if (r < n)
                        *reinterpret_cast<float2*>(Y + (size_t)r * 128 + c) = make_float2(v0, v1);
                    __nv_bfloat162 hi2, lo2;
                    split2(v0, v1, hi2, lo2);
                    uint32_t off = (uint32_t)(r >> 1) * 528 + ((r & 1) * 128 + c) * 2;
                    *(__nv_bfloat162*)(sm + SA_HI + off) = hi2;
                    *(__nv_bfloat162*)(sm + SA_LO + off) = lo2;
                }
            }
            #pragma unroll
            for (int t = 0; t < 16; ++t) {
                int c = nh * 128 + t * 8 + qc;
                acc1[t][0] = sB1[c]; acc1[t][1] = sB1[c + 1];
                acc1[t][2] = sB1[c]; acc1[t][3] = sB1[c + 1];
            }
            n >>= 1;
        }
        if (ph == 4) {
            #pragma unroll
            for (int t = 0; t < 16; ++t) {
                int c = nh * 128 + t * 8 + qc;
                __nv_bfloat162 hi2, lo2;
                split2(lrelu(acc1[t][0]), lrelu(acc1[t][1]), hi2, lo2);
                uint32_t o0 = (uint32_t)(wr + qr) * 528 + c * 2;
                *(__nv_bfloat162*)(sm + SA_HI + o0) = hi2;
                *(__nv_bfloat162*)(sm + SA_LO + o0) = lo2;
                split2(lrelu(acc1[t][2]), lrelu(acc1[t][3]), hi2, lo2);
                uint32_t o1 = (uint32_t)(wr + qr + 8) * 528 + c * 2;
                *(__nv_bfloat162*)(sm + SA_HI + o1) = hi2;
                *(__nv_bfloat162*)(sm + SA_LO + o1) = lo2;
            }
            #pragma unroll
            for (int t = 0; t < 8; ++t) {
                int c = nh * 64 + t * 8 + qc;
                acc2[t][0] = sB2[c]; acc2[t][1] = sB2[c + 1];
                acc2[t][2] = sB2[c]; acc2[t][3] = sB2[c + 1];
            }
        }

        if (g + 1 < GT) { CP_WAIT(1); } else { CP_WAIT(0); }
        __syncthreads();

        const uint32_t slot = wbase + (uint32_t)(g & 1) * 67584u;
        const int kb = (ph < 4 ? ph : ph - 4) * 64;

        #pragma unroll
        for (int j = 0; j < 4; ++j) {
            const int k0 = kb + j * 16;
            unsigned ahi[4], alo[4];
            ldsm4(ahi, aHi + (uint32_t)(k0 + lcol8) * 2);
            ldsm4(alo, aLo + (uint32_t)(k0 + lcol8) * 2);
            if (ph < 4) {
                compute_k256(acc1, ahi, alo, slot + (uint32_t)(j * 16 + lrow) * 528, 33792u, nh, lcol8);
            } else {
                compute_k128(acc2, ahi, alo, slot + (uint32_t)(j * 16 + lrow) * 272, 17408u, nh, lcol8);
            }
        }
        __syncthreads();
        if (g + 2 < GT) load_slab64((g + 2) & 7, wbase, tid);
    }

    #pragma unroll
    for (int t = 0; t < 8; ++t) {
        int c = nh * 64 + t * 8 + qc;
        #pragma unroll
        for (int h = 0; h < 2; ++h) {
            int r = wr + qr + h * 8;
            if (r < 1)
                *reinterpret_cast<float2*>(out + (size_t)r * 128 + c) =
                    make_float2(lrelu(acc2[t][2 * h]), lrelu(acc2[t][2 * h + 1]));
        }
    }
}

extern "C" void kernel_launch(void* const* d_in, const int* in_sizes, int n_in,
                              void* d_out, int out_size)
{
    const float* leaf = (const float*)d_in[0];
    const float* We   = (const float*)d_in[1];
    const float* be   = (const float*)d_in[2];
    const float* W1   = (const float*)d_in[3];
    const float* b1   = (const float*)d_in[4];
    const float* W2   = (const float*)d_in[5];
    const float* b2   = (const float*)d_in[6];
    float* out = (float*)d_out;

    cudaFuncSetAttribute(level_kernel<true>,  cudaFuncAttributeMaxDynamicSharedMemorySize, SMEM_LVL);
    cudaFuncSetAttribute(level_kernel<false>, cudaFuncAttributeMaxDynamicSharedMemorySize, SMEM_LVL);
    cudaFuncSetAttribute(small_kernel, cudaFuncAttributeMaxDynamicSharedMemorySize, SMEM_SMALL);
    cudaFuncSetAttribute(tail_kernel,  cudaFuncAttributeMaxDynamicSharedMemorySize, SMEM_SMALL);

    prep_kernel<<<256, 256>>>(W1, W2, We);

    const size_t leaf_start = (size_t)(1u << DEPTH) - 1;
    float* Yemb = out + leaf_start * 128;

    for (int l = DEPTH - 1; l >= 7; --l) {
        const int n = 1 << l;
        const size_t p0 = (size_t)(1u << l) - 1;
        float* Y = out + p0 * 128;
        const int grid = (n + 63) / 64;
        if (l == DEPTH - 1) {
            level_kernel<true><<<grid, 256, SMEM_LVL>>>(leaf, Y, Yemb, b1, b2, be, n);
        } else if (l >= 14) {
            const float* X = out + (2 * p0 + 1) * 128;
            level_kernel<false><<<grid, 256, SMEM_LVL>>>(X, Y, Yemb, b1, b2, be, n);
        } else {
            const float* X = out + (2 * p0 + 1) * 128;
            small_kernel<<<grid, 256, SMEM_SMALL>>>(X, Y, b1, b2, n);
        }
    }
    tail_kernel<<<1, 256, SMEM_SMALL>>>(out, b1, b2);
}

// round 17
// speedup vs baseline: 1.0233x; 1.0101x over previous
#include <cuda_runtime.h>
#include <cuda_bf16.h>
#include <cstdint>

// R17: R16 + levels 13..7 fused into ONE launch (grid=128, 1 CTA/SM -> all
// resident -> safe software grid barrier between levels; next level's weight
// slabs prefetched before the barrier). Big levels 17..14 and tail unchanged.

static __forceinline__ __device__ float lrelu(float v) { return v > 0.0f ? v : 0.01f * v; }

constexpr int DEPTH = 18;
// big-level kernel smem map
constexpr int SA_HI = 0;        // [64][528B] bf16
constexpr int SA_LO = 33792;
constexpr int W_ST  = 67584;    // 2 slots x 17408
constexpr int SB1   = 102400;
constexpr int SB2   = 103424;
constexpr int SBE   = 103936;
constexpr int SMEM_LVL = 104448;

// slab64 kernels smem map
constexpr int S_W   = 67584;              // 2 slots x 67584
constexpr int S_SB1 = 202752;
constexpr int S_SB2 = 203776;
constexpr int SMEM_SMALL = 204288;

// prepped split weights (row-major bf16)
__device__ __align__(16) __nv_bfloat16 W1hi_d[65536];   // [256][256]
__device__ __align__(16) __nv_bfloat16 W1lo_d[65536];
__device__ __align__(16) __nv_bfloat16 W2hi_d[32768];   // [256][128]
__device__ __align__(16) __nv_bfloat16 W2lo_d[32768];
__device__ __align__(16) __nv_bfloat16 WBhi_d[16384];   // blockdiag(We,We) [64][256]
__device__ __align__(16) __nv_bfloat16 WBlo_d[16384];

// grid-barrier state (generation barrier: cnt returns to 0 every barrier)
__device__ unsigned g_cnt;
__device__ unsigned g_gen;

static __forceinline__ __device__ uint32_t smem_u32(const void* p) {
    uint32_t a;
    asm("{ .reg .u64 t; cvta.to.shared.u64 t, %1; cvt.u32.u64 %0, t; }" : "=r"(a) : "l"(p));
    return a;
}
static __forceinline__ __device__ void cp16(uint32_t d, const void* s) {
    asm volatile("cp.async.cg.shared.global [%0], [%1], 16;" :: "r"(d), "l"(s));
}
#define CP_COMMIT() asm volatile("cp.async.commit_group;" ::: "memory")
#define CP_WAIT(N)  asm volatile("cp.async.wait_group %0;" :: "n"(N) : "memory")

static __forceinline__ __device__ void ldsm4(unsigned* r, uint32_t a) {
    asm volatile("ldmatrix.sync.aligned.m8n8.x4.shared.b16 {%0,%1,%2,%3}, [%4];"
                 : "=r"(r[0]), "=r"(r[1]), "=r"(r[2]), "=r"(r[3]) : "r"(a));
}
static __forceinline__ __device__ void ldsm4t(unsigned* r, uint32_t a) {
    asm volatile("ldmatrix.sync.aligned.m8n8.x4.trans.shared.b16 {%0,%1,%2,%3}, [%4];"
                 : "=r"(r[0]), "=r"(r[1]), "=r"(r[2]), "=r"(r[3]) : "r"(a));
}
static __forceinline__ __device__ void mma_bf16(float* c, const unsigned* a, const unsigned* b) {
    asm volatile("mma.sync.aligned.m16n8k16.row.col.f32.bf16.bf16.f32 "
                 "{%0,%1,%2,%3}, {%4,%5,%6,%7}, {%8,%9}, {%0,%1,%2,%3};"
                 : "+f"(c[0]), "+f"(c[1]), "+f"(c[2]), "+f"(c[3])
                 : "r"(a[0]), "r"(a[1]), "r"(a[2]), "r"(a[3]), "r"(b[0]), "r"(b[1]));
}
static __forceinline__ __device__ void split2(float h0, float h1,
                                              __nv_bfloat162& hi, __nv_bfloat162& lo) {
    hi = __floats2bfloat162_rn(h0, h1);
    lo = __floats2bfloat162_rn(h0 - __bfloat162float(hi.x), h1 - __bfloat162float(hi.y));
}

// all-CTA generation barrier; safe because grid=128 and 1 CTA/SM (all resident)
static __device__ void grid_barrier() {
    __threadfence();
    __syncthreads();
    if (threadIdx.x == 0) {
        unsigned my = *(volatile unsigned*)&g_gen;
        unsigned old = atomicAdd(&g_cnt, 1u);
        if (old == 127u) {
            g_cnt = 0u;
            __threadfence();
            *(volatile unsigned*)&g_gen = my + 1u;
        } else {
            while (*(volatile unsigned*)&g_gen == my) { __nanosleep(64); }
        }
    }
    __syncthreads();
    __threadfence();
}

__global__ void prep_kernel(const float* __restrict__ W1, const float* __restrict__ W2,
                            const float* __restrict__ We) {
    int t = blockIdx.x * 256 + threadIdx.x;
    if (t < 65536) {
        float f = W1[t];
        __nv_bfloat16 hi = __float2bfloat16(f);
        W1hi_d[t] = hi; W1lo_d[t] = __float2bfloat16(f - __bfloat162float(hi));
    }
    if (t < 32768) {
        float f = W2[t];
        __nv_bfloat16 hi = __float2bfloat16(f);
        W2hi_d[t] = hi; W2lo_d[t] = __float2bfloat16(f - __bfloat162float(hi));
    }
    if (t < 16384) {
        int k = t >> 8, c = t & 255;
        float f = 0.0f;
        if (k < 32 && c < 128)   f = We[k * 128 + c];
        if (k >= 32 && c >= 128) f = We[(k - 32) * 128 + (c - 128)];
        __nv_bfloat16 hi = __float2bfloat16(f);
        WBhi_d[t] = hi; WBlo_d[t] = __float2bfloat16(f - __bfloat162float(hi));
    }
}

// ---------- big-level slab loader (W1: 16 k-rows; W2: 32-k-row super-slabs) ----------
template<bool LEAF>
static __forceinline__ __device__ void load_slab(int g, uint32_t base, int tid) {
    uint32_t slot = base + W_ST + (uint32_t)(g & 1) * 17408u;
    constexpr int W2_AT = LEAF ? 20 : 16;
    if (g < W2_AT) {
        const char *hi, *lo;
        if (LEAF && g < 4) {
            hi = (const char*)WBhi_d + (size_t)g * 8192;
            lo = (const char*)WBlo_d + (size_t)g * 8192;
        } else {
            int s = LEAF ? (g - 4) : g;
            hi = (const char*)W1hi_d + (size_t)s * 8192;
            lo = (const char*)W1lo_d + (size_t)s * 8192;
        }
        #pragma unroll
        for (int j = 0; j < 4; ++j) {
            int idx = tid + j * 256;
            int part = idx >> 9, rc = idx & 511, r = rc >> 5, c = rc & 31;
            cp16(slot + part * 8448 + r * 528 + c * 16, (part ? lo : hi) + r * 512 + c * 16);
        }
    } else {
        int s = g - W2_AT;
        const char* hi = (const char*)W2hi_d + (size_t)s * 8192;
        const char* lo = (const char*)W2lo_d + (size_t)s * 8192;
        #pragma unroll
        for (int j = 0; j < 4; ++j) {
            int idx = tid + j * 256;
            int sub = idx >> 9, rc = idx & 511;
            int part = rc >> 8, rr = (rc >> 4) & 15, c = rc & 15;
            cp16(slot + sub * 8704 + part * 4352 + rr * 272 + c * 16,
                 (part ? lo : hi) + sub * 4096 + rr * 256 + c * 16);
        }
    }
    CP_COMMIT();
}

// ---------- slab64 loader: g 0..3 -> W1 64-row slabs, 4..7 -> W2 ----------
static __forceinline__ __device__ void load_slab64(int g, uint32_t wbase, int tid) {
    uint32_t slot = wbase + (uint32_t)(g & 1) * 67584u;
    if (g < 4) {
        const char* hi = (const char*)W1hi_d + (size_t)g * 32768;
        const char* lo = (const char*)W1lo_d + (size_t)g * 32768;
        #pragma unroll
        for (int j = 0; j < 16; ++j) {
            int idx = tid + j * 256;
            int part = idx >> 11, rc = idx & 2047, r = rc >> 5, c = rc & 31;
            cp16(slot + part * 33792 + r * 528 + c * 16, (part ? lo : hi) + r * 512 + c * 16);
        }
    } else {
        const char* hi = (const char*)W2hi_d + (size_t)(g - 4) * 16384;
        const char* lo = (const char*)W2lo_d + (size_t)(g - 4) * 16384;
        #pragma unroll
        for (int j = 0; j < 8; ++j) {
            int idx = tid + j * 256;
            int part = idx >> 10, rc = idx & 1023, r = rc >> 4, c = rc & 15;
            cp16(slot + part * 17408 + r * 272 + c * 16, (part ? lo : hi) + r * 256 + c * 16);
        }
    }
    CP_COMMIT();
}

// ---------- compute sub-stages (16x128 warp tile) ----------
static __forceinline__ __device__ void compute_k256(
    float acc1[16][4], const unsigned ahi[4], const unsigned alo[4],
    uint32_t brow, uint32_t lo_off, int nh, int lcol8)
{
    #pragma unroll
    for (int p = 0; p < 8; ++p) {
        int nb = nh * 128 + p * 16;
        unsigned bh[4], bl[4];
        ldsm4t(bh, brow + (uint32_t)(nb + lcol8) * 2);
        ldsm4t(bl, brow + lo_off + (uint32_t)(nb + lcol8) * 2);
        mma_bf16(acc1[2 * p],     ahi, bh);
        mma_bf16(acc1[2 * p + 1], ahi, bh + 2);
        mma_bf16(acc1[2 * p],     alo, bh);
        mma_bf16(acc1[2 * p + 1], alo, bh + 2);
        mma_bf16(acc1[2 * p],     ahi, bl);
        mma_bf16(acc1[2 * p + 1], ahi, bl + 2);
    }
}
static __forceinline__ __device__ void compute_k128(
    float acc2[8][4], const unsigned ahi[4], const unsigned alo[4],
    uint32_t brow, uint32_t lo_off, int nh, int lcol8)
{
    #pragma unroll
    for (int p = 0; p < 4; ++p) {
        int nb = nh * 64 + p * 16;
        unsigned bh[4], bl[4];
        ldsm4t(bh, brow + (uint32_t)(nb + lcol8) * 2);
        ldsm4t(bl, brow + lo_off + (uint32_t)(nb + lcol8) * 2);
        mma_bf16(acc2[2 * p],     ahi, bh);
        mma_bf16(acc2[2 * p + 1], ahi, bh + 2);
        mma_bf16(acc2[2 * p],     alo, bh);
        mma_bf16(acc2[2 * p + 1], alo, bh + 2);
        mma_bf16(acc2[2 * p],     ahi, bl);
        mma_bf16(acc2[2 * p + 1], ahi, bl + 2);
    }
}

// ---------- big-level kernel (levels 17..14) ----------
template<bool LEAF>
__global__ void __launch_bounds__(256, 2)
level_kernel(const float* __restrict__ X, float* __restrict__ Y,
             float* __restrict__ Yemb,
             const float* __restrict__ b1, const float* __restrict__ b2,
             const float* __restrict__ be, int n)
{
    extern __shared__ __align__(16) char sm[];
    const uint32_t base = smem_u32(sm);
    const int tid = threadIdx.x, wid = tid >> 5, lane = tid & 31;
    const int wr = (wid & 3) * 16;
    const int nh = wid >> 2;
    const int row0 = blockIdx.x * 64;
    const int lrow = lane & 15, lcol8 = (lane >> 4) * 8;
    const int qr = lane >> 2, qc = (lane & 3) * 2;

    constexpr int G = LEAF ? 28 : 24;
    constexpr int EPI1_AT = LEAF ? 20 : 16;

    load_slab<LEAF>(0, base, tid);
    load_slab<LEAF>(1, base, tid);

    ((float*)(sm + SB1))[tid] = b1[tid];
    if (tid < 128) ((float*)(sm + SB2))[tid] = b2[tid];
    if (tid < 128) ((float*)(sm + SBE))[tid] = be[tid];

    if (LEAF) {
        const float* Xb = X + (size_t)row0 * 64;
        for (int idx = tid; idx < 64 * 16; idx += 256) {
            int r = idx >> 4, c4 = idx & 15;
            float4 v = make_float4(0.f, 0.f, 0.f, 0.f);
            if (row0 + r < n) v = reinterpret_cast<const float4*>(Xb)[r * 16 + c4];
            __nv_bfloat162 h0, l0, h1, l1;
            split2(v.x, v.y, h0, l0); split2(v.z, v.w, h1, l1);
            uint32_t off = (uint32_t)r * 528 + c4 * 8;
            *(__nv_bfloat162*)(sm + SA_HI + off)     = h0;
            *(__nv_bfloat162*)(sm + SA_HI + off + 4) = h1;
            *(__nv_bfloat162*)(sm + SA_LO + off)     = l0;
            *(__nv_bfloat162*)(sm + SA_LO + off + 4) = l1;
        }
    } else {
        for (int idx = tid; idx < 64 * 64; idx += 256) {
            int r = idx >> 6, c4 = idx & 63;
            float4 v = make_float4(0.f, 0.f, 0.f, 0.f);
            if (row0 + r < n) v = reinterpret_cast<const float4*>(X)[(size_t)(row0 + r) * 64 + c4];
            __nv_bfloat162 h0, l0, h1, l1;
            split2(v.x, v.y, h0, l0); split2(v.z, v.w, h1, l1);
            uint32_t off = (uint32_t)r * 528 + c4 * 8;
            *(__nv_bfloat162*)(sm + SA_HI + off)     = h0;
            *(__nv_bfloat162*)(sm + SA_HI + off + 4) = h1;
            *(__nv_bfloat162*)(sm + SA_LO + off)     = l0;
            *(__nv_bfloat162*)(sm + SA_LO + off + 4) = l1;
        }
    }
    __syncthreads();

    const float* sB1 = (const float*)(sm + SB1);
    const float* sB2 = (const float*)(sm + SB2);
    const float* sBE = (const float*)(sm + SBE);

    float acc1[16][4];
    float acc2[8][4];
    #pragma unroll
    for (int t = 0; t < 16; ++t) {
        int c = nh * 128 + t * 8 + qc;
        float v0 = LEAF ? sBE[c & 127] : sB1[c];
        float v1 = LEAF ? sBE[(c + 1) & 127] : sB1[c + 1];
        acc1[t][0] = v0; acc1[t][1] = v1; acc1[t][2] = v0; acc1[t][3] = v1;
    }

    const uint32_t aHi = base + SA_HI + (uint32_t)(wr + lrow) * 528;
    const uint32_t aLo = base + SA_LO + (uint32_t)(wr + lrow) * 528;

    for (int g = 0; g < G; ++g) {
        if (LEAF && g == 4) {
            #pragma unroll
            for (int t = 0; t < 16; ++t) {
                int c = nh * 128 + t * 8 + qc;
                float v0 = lrelu(acc1[t][0]), v1 = lrelu(acc1[t][1]);
                float v2 = lrelu(acc1[t][2]), v3 = lrelu(acc1[t][3]);
                __nv_bfloat162 hi2, lo2;
                split2(v0, v1, hi2, lo2);
                uint32_t o0 = (uint32_t)(wr + qr) * 528 + c * 2;
                *(__nv_bfloat162*)(sm + SA_HI + o0) = hi2;
                *(__nv_bfloat162*)(sm + SA_LO + o0) = lo2;
                if (row0 + wr + qr < n)
                    *reinterpret_cast<float2*>(Yemb + (size_t)(row0 + wr + qr) * 256 + c) = make_float2(v0, v1);
                split2(v2, v3, hi2, lo2);
                uint32_t o1 = (uint32_t)(wr + qr + 8) * 528 + c * 2;
                *(__nv_bfloat162*)(sm + SA_HI + o1) = hi2;
                *(__nv_bfloat162*)(sm + SA_LO + o1) = lo2;
                if (row0 + wr + qr + 8 < n)
                    *reinterpret_cast<float2*>(Yemb + (size_t)(row0 + wr + qr + 8) * 256 + c) = make_float2(v2, v3);
            }
            #pragma unroll
            for (int t = 0; t < 16; ++t) {
                int c = nh * 128 + t * 8 + qc;
                acc1[t][0] = sB1[c]; acc1[t][1] = sB1[c + 1];
                acc1[t][2] = sB1[c]; acc1[t][3] = sB1[c + 1];
            }
        }
        if (g == EPI1_AT) {
            #pragma unroll
            for (int t = 0; t < 16; ++t) {
                int c = nh * 128 + t * 8 + qc;
                __nv_bfloat162 hi2, lo2;
                split2(lrelu(acc1[t][0]), lrelu(acc1[t][1]), hi2, lo2);
                uint32_t o0 = (uint32_t)(wr + qr) * 528 + c * 2;
                *(__nv_bfloat162*)(sm + SA_HI + o0) = hi2;
                *(__nv_bfloat162*)(sm + SA_LO + o0) = lo2;
                split2(lrelu(acc1[t][2]), lrelu(acc1[t][3]), hi2, lo2);
                uint32_t o1 = (uint32_t)(wr + qr + 8) * 528 + c * 2;
                *(__nv_bfloat162*)(sm + SA_HI + o1) = hi2;
                *(__nv_bfloat162*)(sm + SA_LO + o1) = lo2;
            }
            #pragma unroll
            for (int t = 0; t < 8; ++t) {
                int c = nh * 64 + t * 8 + qc;
                acc2[t][0] = sB2[c]; acc2[t][1] = sB2[c + 1];
                acc2[t][2] = sB2[c]; acc2[t][3] = sB2[c + 1];
            }
        }

        if (g + 1 < G) { CP_WAIT(1); } else { CP_WAIT(0); }
        __syncthreads();

        const uint32_t slot = base + W_ST + (uint32_t)(g & 1) * 17408u;

        if (g < EPI1_AT) {
            int k0;
            if (LEAF) k0 = (g < 4) ? g * 16 : (g - 4) * 16;
            else      k0 = g * 16;
            unsigned ahi[4], alo[4];
            ldsm4(ahi, aHi + (uint32_t)(k0 + lcol8) * 2);
            ldsm4(alo, aLo + (uint32_t)(k0 + lcol8) * 2);
            compute_k256(acc1, ahi, alo, slot + (uint32_t)lrow * 528, 8448u, nh, lcol8);
        } else {
            const int s = g - EPI1_AT;
            #pragma unroll
            for (int j = 0; j < 2; ++j) {
                const int k0 = s * 32 + j * 16;
                unsigned ahi[4], alo[4];
                ldsm4(ahi, aHi + (uint32_t)(k0 + lcol8) * 2);
                ldsm4(alo, aLo + (uint32_t)(k0 + lcol8) * 2);
                compute_k128(acc2, ahi, alo,
                             slot + (uint32_t)j * 8704 + (uint32_t)lrow * 272, 4352u, nh, lcol8);
            }
        }
        __syncthreads();
        if (g + 2 < G) load_slab<LEAF>(g + 2, base, tid);
    }

    #pragma unroll
    for (int t = 0; t < 8; ++t) {
        int c = nh * 64 + t * 8 + qc;
        int r = row0 + wr + qr;
        if (r < n)
            *reinterpret_cast<float2*>(Y + (size_t)r * 128 + c) =
                make_float2(lrelu(acc2[t][0]), lrelu(acc2[t][1]));
        if (r + 8 < n)
            *reinterpret_cast<float2*>(Y + (size_t)(r + 8) * 128 + c) =
                make_float2(lrelu(acc2[t][2]), lrelu(acc2[t][3]));
    }
}

// fused small levels 13..7: ONE launch, grid=128 (all resident), software
// grid barrier between levels, next level's slabs prefetched pre-barrier.
__global__ void __launch_bounds__(256, 1)
fused_small_kernel(float* __restrict__ out,
                   const float* __restrict__ b1, const float* __restrict__ b2)
{
    extern __shared__ __align__(16) char sm[];
    const uint32_t base = smem_u32(sm);
    const int tid = threadIdx.x, wid = tid >> 5, lane = tid & 31;
    const int wr = (wid & 3) * 16, nh = wid >> 2;
    const int lrow = lane & 15, lcol8 = (lane >> 4) * 8;
    const int qr = lane >> 2, qc = (lane & 3) * 2;
    const uint32_t wbase = base + S_W;
    const int bid = blockIdx.x;

    // prologue: all CTAs active at level 13
    load_slab64(0, wbase, tid);
    load_slab64(1, wbase, tid);
    ((float*)(sm + S_SB1))[tid] = b1[tid];
    if (tid < 128) ((float*)(sm + S_SB2))[tid] = b2[tid];

    const float* sB1 = (const float*)(sm + S_SB1);
    const float* sB2 = (const float*)(sm + S_SB2);
    const uint32_t aHi = base + SA_HI + (uint32_t)(wr + lrow) * 528;
    const uint32_t aLo = base + SA_LO + (uint32_t)(wr + lrow) * 528;

    for (int l = 13; l >= 7; --l) {
        const int ntiles = 1 << (l - 6);
        const bool active = bid < ntiles;
        if (active) {
            const int n = 1 << l;
            const size_t p0 = ((size_t)1 << l) - 1;
            const float* X = out + (2 * p0 + 1) * 128;
            float* Y = out + p0 * 128;
            const int row0 = bid * 64;

            for (int idx = tid; idx < 64 * 64; idx += 256) {
                int r = idx >> 6, c4 = idx & 63;
                float4 v = make_float4(0.f, 0.f, 0.f, 0.f);
                if (row0 + r < n) v = reinterpret_cast<const float4*>(X)[(size_t)(row0 + r) * 64 + c4];
                __nv_bfloat162 h0, l0, h1, l1;
                split2(v.x, v.y, h0, l0); split2(v.z, v.w, h1, l1);
                uint32_t off = (uint32_t)r * 528 + c4 * 8;
                *(__nv_bfloat162*)(sm + SA_HI + off)     = h0;
                *(__nv_bfloat162*)(sm + SA_HI + off + 4) = h1;
                *(__nv_bfloat162*)(sm + SA_LO + off)     = l0;
                *(__nv_bfloat162*)(sm + SA_LO + off + 4) = l1;
            }
            __syncthreads();

            float acc1[16][4], acc2[8][4];
            #pragma unroll
            for (int t = 0; t < 16; ++t) {
                int c = nh * 128 + t * 8 + qc;
                acc1[t][0] = sB1[c]; acc1[t][1] = sB1[c + 1];
                acc1[t][2] = sB1[c]; acc1[t][3] = sB1[c + 1];
            }

            for (int g = 0; g < 8; ++g) {
                if (g == 4) {
                    #pragma unroll
                    for (int t = 0; t < 16; ++t) {
                        int c = nh * 128 + t * 8 + qc;
                        __nv_bfloat162 hi2, lo2;
                        split2(lrelu(acc1[t][0]), lrelu(acc1[t][1]), hi2, lo2);
                        uint32_t o0 = (uint32_t)(wr + qr) * 528 + c * 2;
                        *(__nv_bfloat162*)(sm + SA_HI + o0) = hi2;
                        *(__nv_bfloat162*)(sm + SA_LO + o0) = lo2;
                        split2(lrelu(acc1[t][2]), lrelu(acc1[t][3]), hi2, lo2);
                        uint32_t o1 = (uint32_t)(wr + qr + 8) * 528 + c * 2;
                        *(__nv_bfloat162*)(sm + SA_HI + o1) = hi2;
                        *(__nv_bfloat162*)(sm + SA_LO + o1) = lo2;
                    }
                    #pragma unroll
                    for (int t = 0; t < 8; ++t) {
                        int c = nh * 64 + t * 8 + qc;
                        acc2[t][0] = sB2[c]; acc2[t][1] = sB2[c + 1];
                        acc2[t][2] = sB2[c]; acc2[t][3] = sB2[c + 1];
                    }
                }

                if (g + 1 < 8) { CP_WAIT(1); } else { CP_WAIT(0); }
                __syncthreads();

                const uint32_t slot = wbase + (uint32_t)(g & 1) * 67584u;
                const int kb = (g < 4 ? g : g - 4) * 64;

                #pragma unroll
                for (int j = 0; j < 4; ++j) {
                    const int k0 = kb + j * 16;
                    unsigned ahi[4], alo[4];
                    ldsm4(ahi, aHi + (uint32_t)(k0 + lcol8) * 2);
                    ldsm4(alo, aLo + (uint32_t)(k0 + lcol8) * 2);
                    if (g < 4) {
                        compute_k256(acc1, ahi, alo, slot + (uint32_t)(j * 16 + lrow) * 528, 33792u, nh, lcol8);
                    } else {
                        compute_k128(acc2, ahi, alo, slot + (uint32_t)(j * 16 + lrow) * 272, 17408u, nh, lcol8);
                    }
                }
                __syncthreads();
                if (g + 2 < 8) load_slab64(g + 2, wbase, tid);
            }

            #pragma unroll
            for (int t = 0; t < 8; ++t) {
                int c = nh * 64 + t * 8 + qc;
                int r = row0 + wr + qr;
                if (r < n)
                    *reinterpret_cast<float2*>(Y + (size_t)r * 128 + c) =
                        make_float2(lrelu(acc2[t][0]), lrelu(acc2[t][1]));
                if (r + 8 < n)
                    *reinterpret_cast<float2*>(Y + (size_t)(r + 8) * 128 + c) =
                        make_float2(lrelu(acc2[t][2]), lrelu(acc2[t][3]));
            }

            // prefetch next level's first slabs (weights independent of barrier)
            if (l > 7 && bid < (ntiles >> 1)) {
                load_slab64(0, wbase, tid);
                load_slab64(1, wbase, tid);
            }
        }
        if (l > 7) grid_barrier();
    }
}

// tail: levels 6..0 in one CTA, 56 stages, K-slab 64.
__global__ void __launch_bounds__(256, 1)
tail_kernel(float* __restrict__ out,
            const float* __restrict__ b1, const float* __restrict__ b2)
{
    extern __shared__ __align__(16) char sm[];
    const uint32_t base = smem_u32(sm);
    const int tid = threadIdx.x, wid = tid >> 5, lane = tid & 31;
    const int wr = (wid & 3) * 16, nh = wid >> 2;
    const int lrow = lane & 15, lcol8 = (lane >> 4) * 8;
    const int qr = lane >> 2, qc = (lane & 3) * 2;
    const uint32_t wbase = base + S_W;

    load_slab64(0, wbase, tid);
    load_slab64(1, wbase, tid);

    ((float*)(sm + S_SB1))[tid] = b1[tid];
    if (tid < 128) ((float*)(sm + S_SB2))[tid] = b2[tid];

    {
        const float* X = out + 127 * 128;
        for (int idx = tid; idx < 64 * 64; idx += 256) {
            int r = idx >> 6, c4 = idx & 63;
            float4 v = reinterpret_cast<const float4*>(X)[r * 64 + c4];
            __nv_bfloat162 h0, l0, h1, l1;
            split2(v.x, v.y, h0, l0); split2(v.z, v.w, h1, l1);
            uint32_t off = (uint32_t)r * 528 + c4 * 8;
            *(__nv_bfloat162*)(sm + SA_HI + off)     = h0;
            *(__nv_bfloat162*)(sm + SA_HI + off + 4) = h1;
            *(__nv_bfloat162*)(sm + SA_LO + off)     = l0;
            *(__nv_bfloat162*)(sm + SA_LO + off + 4) = l1;
        }
    }
    __syncthreads();

    const float* sB1 = (const float*)(sm + S_SB1);
    const float* sB2 = (const float*)(sm + S_SB2);

    float acc1[16][4], acc2[8][4];
    #pragma unroll
    for (int t = 0; t < 16; ++t) {
        int c = nh * 128 + t * 8 + qc;
        acc1[t][0] = sB1[c]; acc1[t][1] = sB1[c + 1];
        acc1[t][2] = sB1[c]; acc1[t][3] = sB1[c + 1];
    }

    const uint32_t aHi = base + SA_HI + (uint32_t)(wr + lrow) * 528;
    const uint32_t aLo = base + SA_LO + (uint32_t)(wr + lrow) * 528;

    int n = 64;
    constexpr int GT = 7 * 8;
    for (int g = 0; g < GT; ++g) {
        const int ph = g & 7;
        if (ph == 0 && g > 0) {
            const int lvDone = 7 - (g >> 3);
            float* Y = out + (((size_t)1 << lvDone) - 1) * 128;
            #pragma unroll
            for (int t = 0; t < 8; ++t) {
                int c = nh * 64 + t * 8 + qc;
                #pragma unroll
                for (int h = 0; h < 2; ++h) {
                    int r = wr + qr + h * 8;
                    float v0 = lrelu(acc2[t][2 * h]);
                    float v1 = lrelu(acc2[t][2 * h + 1]);
                    if (r < n)
                        *reinterpret_cast<float2*>(Y + (size_t)r * 128 + c) = make_float2(v0, v1);
                    __nv_bfloat162 hi2, lo2;
                    split2(v0, v1, hi2, lo2);
                    uint32_t off = (uint32_t)(r >> 1) * 528 + ((r & 1) * 128 + c) * 2;
                    *(__nv_bfloat162*)(sm + SA_HI + off) = hi2;
                    *(__nv_bfloat162*)(sm + SA_LO + off) = lo2;
                }
            }
            #pragma unroll
            for (int t = 0; t < 16; ++t) {
                int c = nh * 128 + t * 8 + qc;
                acc1[t][0] = sB1[c]; acc1[t][1] = sB1[c + 1];
                acc1[t][2] = sB1[c]; acc1[t][3] = sB1[c + 1];
            }
            n >>= 1;
        }
        if (ph == 4) {
            #pragma unroll
            for (int t = 0; t < 16; ++t) {
                int c = nh * 128 + t * 8 + qc;
                __nv_bfloat162 hi2, lo2;
                split2(lrelu(acc1[t][0]), lrelu(acc1[t][1]), hi2, lo2);
                uint32_t o0 = (uint32_t)(wr + qr) * 528 + c * 2;
                *(__nv_bfloat162*)(sm + SA_HI + o0) = hi2;
                *(__nv_bfloat162*)(sm + SA_LO + o0) = lo2;
                split2(lrelu(acc1[t][2]), lrelu(acc1[t][3]), hi2, lo2);
                uint32_t o1 = (uint32_t)(wr + qr + 8) * 528 + c * 2;
                *(__nv_bfloat162*)(sm + SA_HI + o1) = hi2;
                *(__nv_bfloat162*)(sm + SA_LO + o1) = lo2;
            }
            #pragma unroll
            for (int t = 0; t < 8; ++t) {
                int c = nh * 64 + t * 8 + qc;
                acc2[t][0] = sB2[c]; acc2[t][1] = sB2[c + 1];
                acc2[t][2] = sB2[c]; acc2[t][3] = sB2[c + 1];
            }
        }

        if (g + 1 < GT) { CP_WAIT(1); } else { CP_WAIT(0); }
        __syncthreads();

        const uint32_t slot = wbase + (uint32_t)(g & 1) * 67584u;
        const int kb = (ph < 4 ? ph : ph - 4) * 64;

        #pragma unroll
        for (int j = 0; j < 4; ++j) {
            const int k0 = kb + j * 16;
            unsigned ahi[4], alo[4];
            ldsm4(ahi, aHi + (uint32_t)(k0 + lcol8) * 2);
            ldsm4(alo, aLo + (uint32_t)(k0 + lcol8) * 2);
            if (ph < 4) {
                compute_k256(acc1, ahi, alo, slot + (uint32_t)(j * 16 + lrow) * 528, 33792u, nh, lcol8);
            } else {
                compute_k128(acc2, ahi, alo, slot + (uint32_t)(j * 16 + lrow) * 272, 17408u, nh, lcol8);
            }
        }
        __syncthreads();
        if (g + 2 < GT) load_slab64((g + 2) & 7, wbase, tid);
    }

    #pragma unroll
    for (int t = 0; t < 8; ++t) {
        int c = nh * 64 + t * 8 + qc;
        #pragma unroll
        for (int h = 0; h < 2; ++h) {
            int r = wr + qr + h * 8;
            if (r < 1)
                *reinterpret_cast<float2*>(out + (size_t)r * 128 + c) =
                    make_float2(lrelu(acc2[t][2 * h]), lrelu(acc2[t][2 * h + 1]));
        }
    }
}

extern "C" void kernel_launch(void* const* d_in, const int* in_sizes, int n_in,
                              void* d_out, int out_size)
{
    const float* leaf = (const float*)d_in[0];
    const float* We   = (const float*)d_in[1];
    const float* be   = (const float*)d_in[2];
    const float* W1   = (const float*)d_in[3];
    const float* b1   = (const float*)d_in[4];
    const float* W2   = (const float*)d_in[5];
    const float* b2   = (const float*)d_in[6];
    float* out = (float*)d_out;

    cudaFuncSetAttribute(level_kernel<true>,  cudaFuncAttributeMaxDynamicSharedMemorySize, SMEM_LVL);
    cudaFuncSetAttribute(level_kernel<false>, cudaFuncAttributeMaxDynamicSharedMemorySize, SMEM_LVL);
    cudaFuncSetAttribute(fused_small_kernel,  cudaFuncAttributeMaxDynamicSharedMemorySize, SMEM_SMALL);
    cudaFuncSetAttribute(tail_kernel,         cudaFuncAttributeMaxDynamicSharedMemorySize, SMEM_SMALL);

    prep_kernel<<<256, 256>>>(W1, W2, We);

    const size_t leaf_start = (size_t)(1u << DEPTH) - 1;
    float* Yemb = out + leaf_start * 128;

    for (int l = DEPTH - 1; l >= 14; --l) {
        const int n = 1 << l;
        const size_t p0 = (size_t)(1u << l) - 1;
        float* Y = out + p0 * 128;
        const int grid = (n + 63) / 64;
        if (l == DEPTH - 1) {
            level_kernel<true><<<grid, 256, SMEM_LVL>>>(leaf, Y, Yemb, b1, b2, be, n);
        } else {
            const float* X = out + (2 * p0 + 1) * 128;
            level_kernel<false><<<grid, 256, SMEM_LVL>>>(X, Y, Yemb, b1, b2, be, n);
        }
    }
    fused_small_kernel<<<128, 256, SMEM_SMALL>>>(out, b1, b2);
    tail_kernel<<<1, 256, SMEM_SMALL>>>(out, b1, b2);
}